// round 4
// baseline (speedup 1.0000x reference)
#include <cuda_runtime.h>
#include <cuda_bf16.h>

#define BATCH 2
#define SEQ   2048
#define HID   1024
#define NHEAD 16
#define HDIM  64
#define MROWS (BATCH*SEQ)   // 4096

// Scratch (allocation-free rule)
__device__ float g_q[MROWS*HID];
__device__ float g_k[MROWS*HID];
__device__ float g_v[MROWS*HID];
__device__ float g_ctx[MROWS*HID];

// ---------------------------------------------------------------------------
// helpers: bf16x2 packing, fp32 -> (hi,lo) bf16 split, m16n8k16 mma
// ---------------------------------------------------------------------------
__device__ __forceinline__ unsigned pack2(__nv_bfloat16 a, __nv_bfloat16 b) {
    __nv_bfloat162 t(a, b);   // .x = low half = even element
    return *reinterpret_cast<unsigned*>(&t);
}

__device__ __forceinline__ void split2(float x0, float x1,
                                       unsigned &hi, unsigned &lo) {
    __nv_bfloat16 h0 = __float2bfloat16(x0);
    __nv_bfloat16 h1 = __float2bfloat16(x1);
    __nv_bfloat16 l0 = __float2bfloat16(x0 - __bfloat162float(h0));
    __nv_bfloat16 l1 = __float2bfloat16(x1 - __bfloat162float(h1));
    hi = pack2(h0, h1);
    lo = pack2(l0, l1);
}

__device__ __forceinline__ void mma16816(float* c, const unsigned* a,
                                         unsigned b0, unsigned b1) {
    asm volatile(
        "mma.sync.aligned.m16n8k16.row.col.f32.bf16.bf16.f32 "
        "{%0,%1,%2,%3},{%4,%5,%6,%7},{%8,%9},{%0,%1,%2,%3};\n"
        : "+f"(c[0]), "+f"(c[1]), "+f"(c[2]), "+f"(c[3])
        : "r"(a[0]), "r"(a[1]), "r"(a[2]), "r"(a[3]), "r"(b0), "r"(b1));
}

// 3-term emulated-fp32 mma: c += Ahi*Bhi + Alo*Bhi + Ahi*Blo
__device__ __forceinline__ void mma3(float* c,
                                     const unsigned* ah, const unsigned* al,
                                     unsigned bh0, unsigned bh1,
                                     unsigned bl0, unsigned bl1) {
    mma16816(c, ah, bh0, bh1);
    mma16816(c, al, bh0, bh1);
    mma16816(c, ah, bl0, bl1);
}

// ---------------------------------------------------------------------------
// Tensor-core GEMM: C = A[M,K] @ W[N,K]^T + bias[N]
// CTA tile 128(M) x 64(N), k-step 32, 256 threads = 8 warps (4m x 2n),
// warp tile 32x32 (2 m-tiles x 4 n-tiles of m16n8).
// Smem holds bf16x2 pairs: pitch 20 u32 per 16-pair row (conflict-free).
// ---------------------------------------------------------------------------
__global__ __launch_bounds__(256) void gemm_tc_kernel(
    const float* __restrict__ A, const float* __restrict__ W,
    const float* __restrict__ bias, float* __restrict__ Cout, int headSplit)
{
    __shared__ unsigned sAhi[128 * 20];
    __shared__ unsigned sAlo[128 * 20];
    __shared__ unsigned sWhi[64 * 20];
    __shared__ unsigned sWlo[64 * 20];

    const int tid  = threadIdx.x;
    const int lane = tid & 31;
    const int warp = tid >> 5;
    const int wm   = warp >> 1;          // 0..3
    const int wn   = warp & 1;           // 0..1
    const int r    = lane >> 2;          // 0..7
    const int c    = lane & 3;           // 0..3
    const int m0   = blockIdx.y * 128;
    const int n0   = blockIdx.x * 64;

    float acc[2][4][4] = {};

    for (int k0 = 0; k0 < HID; k0 += 32) {
        // load A tile: 128 rows x 16 pairs
        #pragma unroll
        for (int j = 0; j < 8; j++) {
            int idx = tid + j * 256;          // 0..2047
            int row = idx >> 4, p = idx & 15;
            float2 v = *(const float2*)(A + (size_t)(m0 + row) * HID + k0 + p * 2);
            split2(v.x, v.y, sAhi[row * 20 + p], sAlo[row * 20 + p]);
        }
        // load W tile: 64 rows x 16 pairs
        #pragma unroll
        for (int j = 0; j < 4; j++) {
            int idx = tid + j * 256;          // 0..1023
            int row = idx >> 4, p = idx & 15;
            float2 v = *(const float2*)(W + (size_t)(n0 + row) * HID + k0 + p * 2);
            split2(v.x, v.y, sWhi[row * 20 + p], sWlo[row * 20 + p]);
        }
        __syncthreads();

        #pragma unroll
        for (int kk = 0; kk < 2; kk++) {
            unsigned ah[2][4], al[2][4];
            #pragma unroll
            for (int mt = 0; mt < 2; mt++) {
                int base = wm * 32 + mt * 16;
                ah[mt][0] = sAhi[(base + r)     * 20 + kk * 8 + c];
                ah[mt][1] = sAhi[(base + r + 8) * 20 + kk * 8 + c];
                ah[mt][2] = sAhi[(base + r)     * 20 + kk * 8 + c + 4];
                ah[mt][3] = sAhi[(base + r + 8) * 20 + kk * 8 + c + 4];
                al[mt][0] = sAlo[(base + r)     * 20 + kk * 8 + c];
                al[mt][1] = sAlo[(base + r + 8) * 20 + kk * 8 + c];
                al[mt][2] = sAlo[(base + r)     * 20 + kk * 8 + c + 4];
                al[mt][3] = sAlo[(base + r + 8) * 20 + kk * 8 + c + 4];
            }
            #pragma unroll
            for (int nt = 0; nt < 4; nt++) {
                int n = wn * 32 + nt * 8 + r;
                unsigned bh0 = sWhi[n * 20 + kk * 8 + c];
                unsigned bh1 = sWhi[n * 20 + kk * 8 + c + 4];
                unsigned bl0 = sWlo[n * 20 + kk * 8 + c];
                unsigned bl1 = sWlo[n * 20 + kk * 8 + c + 4];
                #pragma unroll
                for (int mt = 0; mt < 2; mt++)
                    mma3(acc[mt][nt], ah[mt], al[mt], bh0, bh1, bl0, bl1);
            }
        }
        __syncthreads();
    }

    // epilogue
    #pragma unroll
    for (int mt = 0; mt < 2; mt++) {
        #pragma unroll
        for (int nt = 0; nt < 4; nt++) {
            int row = m0 + wm * 32 + mt * 16 + r;
            int col = n0 + wn * 32 + nt * 8 + 2 * c;
            float b0 = bias[col], b1 = bias[col + 1];
            float v00 = acc[mt][nt][0] + b0;
            float v01 = acc[mt][nt][1] + b1;
            float v10 = acc[mt][nt][2] + b0;
            float v11 = acc[mt][nt][3] + b1;
            if (headSplit) {
                int h = col >> 6, d = col & 63;
                int bb0 = row >> 11, s0 = row & (SEQ - 1);
                int bb1 = (row + 8) >> 11, s1 = (row + 8) & (SEQ - 1);
                size_t base0 = (((size_t)(bb0 * NHEAD + h)) * SEQ + s0) * HDIM + d;
                size_t base1 = (((size_t)(bb1 * NHEAD + h)) * SEQ + s1) * HDIM + d;
                Cout[base0] = v00; Cout[base0 + 1] = v01;
                Cout[base1] = v10; Cout[base1 + 1] = v11;
            } else {
                Cout[(size_t)row * HID + col]           = v00;
                Cout[(size_t)row * HID + col + 1]       = v01;
                Cout[(size_t)(row + 8) * HID + col]     = v10;
                Cout[(size_t)(row + 8) * HID + col + 1] = v11;
            }
        }
    }
}

// ---------------------------------------------------------------------------
// Tensor-core fused attention. CTA = 128 q-rows of one (b,h); 8 warps x 16 q.
// Online softmax over 32 k-tiles of 64. All matmuls bf16x3 emulated fp32.
// Smem (dynamic): K [kcol][dpair], Vt [d][kpair], P [qrow][kpair] (hi/lo).
// ---------------------------------------------------------------------------
__global__ __launch_bounds__(256) void attn_tc_kernel(
    const float* __restrict__ mask, float* __restrict__ ctx)
{
    extern __shared__ unsigned smU[];
    unsigned* sKhi = smU;                  // 64*36
    unsigned* sKlo = sKhi + 64 * 36;
    unsigned* sVhi = sKlo + 64 * 36;       // [d][kpair]
    unsigned* sVlo = sVhi + 64 * 36;
    unsigned* sPhi = sVlo + 64 * 36;       // 128*36
    unsigned* sPlo = sPhi + 128 * 36;

    const int tid  = threadIdx.x;
    const int lane = tid & 31;
    const int warp = tid >> 5;
    const int r    = lane >> 2;
    const int c    = lane & 3;
    const int bh   = blockIdx.y;           // 0..31
    const int bb   = bh >> 4;
    const int h    = bh & 15;
    const int q0   = blockIdx.x * 128;

    const float* Qp = g_q + (size_t)bh * SEQ * HDIM;
    const float* Kp = g_k + (size_t)bh * SEQ * HDIM;
    const float* Vp = g_v + (size_t)bh * SEQ * HDIM;

    // ---- Q fragments in registers (hi/lo), 16 q-rows per warp ----
    unsigned qh[4][4], ql[4][4];
    {
        int qr  = q0 + warp * 16 + r;
        int qr8 = qr + 8;
        #pragma unroll
        for (int kk = 0; kk < 4; kk++) {
            float2 v0 = *(const float2*)(Qp + (size_t)qr  * HDIM + (kk * 8 + c) * 2);
            float2 v1 = *(const float2*)(Qp + (size_t)qr8 * HDIM + (kk * 8 + c) * 2);
            float2 v2 = *(const float2*)(Qp + (size_t)qr  * HDIM + (kk * 8 + c + 4) * 2);
            float2 v3 = *(const float2*)(Qp + (size_t)qr8 * HDIM + (kk * 8 + c + 4) * 2);
            split2(v0.x, v0.y, qh[kk][0], ql[kk][0]);
            split2(v1.x, v1.y, qh[kk][1], ql[kk][1]);
            split2(v2.x, v2.y, qh[kk][2], ql[kk][2]);
            split2(v3.x, v3.y, qh[kk][3], ql[kk][3]);
        }
    }

    float o[8][4] = {};
    float m_lo = -1e30f, m_hi = -1e30f, l_lo = 0.0f, l_hi = 0.0f;

    for (int kt = 0; kt < SEQ / 64; kt++) {
        const int k0 = kt * 64;

        // ---- load K (row-major pairs) and V (transposed, bf16 halves) ----
        #pragma unroll
        for (int j = 0; j < 8; j++) {
            int idx = tid + j * 256;          // 0..2047
            int row = idx >> 5, p = idx & 31;
            float2 kv = *(const float2*)(Kp + (size_t)(k0 + row) * HDIM + p * 2);
            split2(kv.x, kv.y, sKhi[row * 36 + p], sKlo[row * 36 + p]);

            float2 vv = *(const float2*)(Vp + (size_t)(k0 + row) * HDIM + p * 2);
            // V[row][2p], V[row][2p+1] -> Vt[2p][row], Vt[2p+1][row]
            __nv_bfloat16 h0 = __float2bfloat16(vv.x);
            __nv_bfloat16 h1 = __float2bfloat16(vv.y);
            __nv_bfloat16 l0 = __float2bfloat16(vv.x - __bfloat162float(h0));
            __nv_bfloat16 l1 = __float2bfloat16(vv.y - __bfloat162float(h1));
            int pair = row >> 1, half = row & 1;
            ((__nv_bfloat16*)sVhi)[((2 * p)     * 36 + pair) * 2 + half] = h0;
            ((__nv_bfloat16*)sVhi)[((2 * p + 1) * 36 + pair) * 2 + half] = h1;
            ((__nv_bfloat16*)sVlo)[((2 * p)     * 36 + pair) * 2 + half] = l0;
            ((__nv_bfloat16*)sVlo)[((2 * p + 1) * 36 + pair) * 2 + half] = l1;
        }
        __syncthreads();

        // ---- S = Q K^T (16 x 64 per warp) ----
        float s[8][4] = {};
        #pragma unroll
        for (int kk = 0; kk < 4; kk++) {
            #pragma unroll
            for (int nt = 0; nt < 8; nt++) {
                int n = nt * 8 + r;
                unsigned bh0 = sKhi[n * 36 + kk * 8 + c];
                unsigned bh1 = sKhi[n * 36 + kk * 8 + c + 4];
                unsigned bl0 = sKlo[n * 36 + kk * 8 + c];
                unsigned bl1 = sKlo[n * 36 + kk * 8 + c + 4];
                mma3(s[nt], qh[kk], ql[kk], bh0, bh1, bl0, bl1);
            }
        }

        // ---- scale + mask + online softmax ----
        float tmax_lo = -1e30f, tmax_hi = -1e30f;
        #pragma unroll
        for (int nt = 0; nt < 8; nt++) {
            int col = k0 + nt * 8 + 2 * c;
            float mk0 = mask[(size_t)bb * SEQ + col];
            float mk1 = mask[(size_t)bb * SEQ + col + 1];
            s[nt][0] = s[nt][0] * 0.125f + mk0;
            s[nt][1] = s[nt][1] * 0.125f + mk1;
            s[nt][2] = s[nt][2] * 0.125f + mk0;
            s[nt][3] = s[nt][3] * 0.125f + mk1;
            tmax_lo = fmaxf(tmax_lo, fmaxf(s[nt][0], s[nt][1]));
            tmax_hi = fmaxf(tmax_hi, fmaxf(s[nt][2], s[nt][3]));
        }
        #pragma unroll
        for (int d = 1; d <= 2; d <<= 1) {
            tmax_lo = fmaxf(tmax_lo, __shfl_xor_sync(0xffffffffu, tmax_lo, d));
            tmax_hi = fmaxf(tmax_hi, __shfl_xor_sync(0xffffffffu, tmax_hi, d));
        }
        float mn_lo = fmaxf(m_lo, tmax_lo);
        float mn_hi = fmaxf(m_hi, tmax_hi);
        float scl_lo = __expf(m_lo - mn_lo);
        float scl_hi = __expf(m_hi - mn_hi);
        m_lo = mn_lo; m_hi = mn_hi;

        float sum_lo = 0.0f, sum_hi = 0.0f;
        int prow = warp * 16 + r;
        #pragma unroll
        for (int nt = 0; nt < 8; nt++) {
            float p0 = __expf(s[nt][0] - m_lo);
            float p1 = __expf(s[nt][1] - m_lo);
            float p2 = __expf(s[nt][2] - m_hi);
            float p3 = __expf(s[nt][3] - m_hi);
            sum_lo += p0 + p1;
            sum_hi += p2 + p3;
            split2(p0, p1, sPhi[prow * 36 + nt * 4 + c],
                           sPlo[prow * 36 + nt * 4 + c]);
            split2(p2, p3, sPhi[(prow + 8) * 36 + nt * 4 + c],
                           sPlo[(prow + 8) * 36 + nt * 4 + c]);
        }
        #pragma unroll
        for (int d = 1; d <= 2; d <<= 1) {
            sum_lo += __shfl_xor_sync(0xffffffffu, sum_lo, d);
            sum_hi += __shfl_xor_sync(0xffffffffu, sum_hi, d);
        }
        l_lo = l_lo * scl_lo + sum_lo;
        l_hi = l_hi * scl_hi + sum_hi;

        #pragma unroll
        for (int nt = 0; nt < 8; nt++) {
            o[nt][0] *= scl_lo; o[nt][1] *= scl_lo;
            o[nt][2] *= scl_hi; o[nt][3] *= scl_hi;
        }
        __syncwarp();

        // ---- O += P V (contraction over 64 k-cols) ----
        int pbase = warp * 16;
        #pragma unroll
        for (int kk = 0; kk < 4; kk++) {
            unsigned ah[4], al[4];
            ah[0] = sPhi[(pbase + r)     * 36 + kk * 8 + c];
            ah[1] = sPhi[(pbase + r + 8) * 36 + kk * 8 + c];
            ah[2] = sPhi[(pbase + r)     * 36 + kk * 8 + c + 4];
            ah[3] = sPhi[(pbase + r + 8) * 36 + kk * 8 + c + 4];
            al[0] = sPlo[(pbase + r)     * 36 + kk * 8 + c];
            al[1] = sPlo[(pbase + r + 8) * 36 + kk * 8 + c];
            al[2] = sPlo[(pbase + r)     * 36 + kk * 8 + c + 4];
            al[3] = sPlo[(pbase + r + 8) * 36 + kk * 8 + c + 4];
            #pragma unroll
            for (int nt = 0; nt < 8; nt++) {
                int d = nt * 8 + r;
                unsigned bh0 = sVhi[d * 36 + kk * 8 + c];
                unsigned bh1 = sVhi[d * 36 + kk * 8 + c + 4];
                unsigned bl0 = sVlo[d * 36 + kk * 8 + c];
                unsigned bl1 = sVlo[d * 36 + kk * 8 + c + 4];
                mma3(o[nt], ah, al, bh0, bh1, bl0, bl1);
            }
        }
        __syncthreads();
    }

    // ---- epilogue: ctx[b*SEQ+q][h*64+d] = O / l ----
    float inv_lo = 1.0f / l_lo;
    float inv_hi = 1.0f / l_hi;
    size_t mrow  = (size_t)bb * SEQ + q0 + warp * 16 + r;
    size_t mrow8 = mrow + 8;
    #pragma unroll
    for (int nt = 0; nt < 8; nt++) {
        int col = h * 64 + nt * 8 + 2 * c;
        ctx[mrow  * HID + col]     = o[nt][0] * inv_lo;
        ctx[mrow  * HID + col + 1] = o[nt][1] * inv_lo;
        ctx[mrow8 * HID + col]     = o[nt][2] * inv_hi;
        ctx[mrow8 * HID + col + 1] = o[nt][3] * inv_hi;
    }
}

// ---------------------------------------------------------------------------

extern "C" void kernel_launch(void* const* d_in, const int* in_sizes, int n_in,
                              void* d_out, int out_size)
{
    const float* hs   = (const float*)d_in[0];
    const float* mask = (const float*)d_in[1];
    const float* Wq   = (const float*)d_in[2];
    const float* bq   = (const float*)d_in[3];
    const float* Wk   = (const float*)d_in[4];
    const float* bk   = (const float*)d_in[5];
    const float* Wv   = (const float*)d_in[6];
    const float* bv   = (const float*)d_in[7];
    const float* Wo   = (const float*)d_in[8];
    const float* bo   = (const float*)d_in[9];
    float* out = (float*)d_out;

    float *qptr, *kptr, *vptr, *cptr;
    cudaGetSymbolAddress((void**)&qptr, g_q);
    cudaGetSymbolAddress((void**)&kptr, g_k);
    cudaGetSymbolAddress((void**)&vptr, g_v);
    cudaGetSymbolAddress((void**)&cptr, g_ctx);

    const int attn_smem = (4 * 64 * 36 + 2 * 128 * 36) * (int)sizeof(unsigned); // 73,728 B
    cudaFuncSetAttribute(attn_tc_kernel,
                         cudaFuncAttributeMaxDynamicSharedMemorySize, attn_smem);

    dim3 blk(256);
    dim3 gGemm(HID / 64, MROWS / 128);    // (16, 32)

    gemm_tc_kernel<<<gGemm, blk>>>(hs, Wq, bq, qptr, 1);
    gemm_tc_kernel<<<gGemm, blk>>>(hs, Wk, bk, kptr, 1);
    gemm_tc_kernel<<<gGemm, blk>>>(hs, Wv, bv, vptr, 1);

    dim3 gAttn(SEQ / 128, BATCH * NHEAD); // (16, 32)
    attn_tc_kernel<<<gAttn, blk, attn_smem>>>(mask, cptr);

    gemm_tc_kernel<<<gGemm, blk>>>(cptr, Wo, bo, out, 0);
}

// round 6
// speedup vs baseline: 1.0418x; 1.0418x over previous
#include <cuda_runtime.h>
#include <cuda_fp16.h>
#include <cstdint>

#define BATCH 2
#define SEQ   2048
#define HID   1024
#define NHEAD 16
#define HDIM  64
#define MROWS (BATCH*SEQ)   // 4096
#define BH    (BATCH*NHEAD) // 32

// ---------------- device scratch (allocation-free rule) ----------------
// presplit fp16 operands
__device__ __half g_hsh[MROWS*HID], g_hsl[MROWS*HID];     // hidden states hi/lo
__device__ __half g_wh[4*HID*HID],  g_wl[4*HID*HID];      // Wq,Wk,Wv,Wo hi/lo
__device__ __half g_qh[BH*SEQ*HDIM], g_ql[BH*SEQ*HDIM];   // Q split  [bh][s][d]
__device__ __half g_kf[BH*SEQ*HDIM];                      // K plain  [bh][s][d]
__device__ __half g_vh[BH*SEQ*HDIM], g_vl[BH*SEQ*HDIM];   // V split  [bh][s][d]
__device__ __half g_vth[BH*HDIM*SEQ], g_vtl[BH*HDIM*SEQ]; // V^T split [bh][d][s]
__device__ __half g_cxh[MROWS*HID], g_cxl[MROWS*HID];     // ctx split [m][n]

// ---------------- helpers ----------------
__device__ __forceinline__ unsigned pack2h(__half a, __half b) {
    __half2 t(a, b);
    return *reinterpret_cast<unsigned*>(&t);
}
__device__ __forceinline__ void split2h(float x0, float x1, unsigned &hi, unsigned &lo) {
    __half h0 = __float2half_rn(x0);
    __half h1 = __float2half_rn(x1);
    __half l0 = __float2half_rn(x0 - __half2float(h0));
    __half l1 = __float2half_rn(x1 - __half2float(h1));
    hi = pack2h(h0, h1); lo = pack2h(l0, l1);
}
__device__ __forceinline__ void mma_h(float* c, const unsigned* a,
                                      unsigned b0, unsigned b1) {
    asm volatile(
        "mma.sync.aligned.m16n8k16.row.col.f32.f16.f16.f32 "
        "{%0,%1,%2,%3},{%4,%5,%6,%7},{%8,%9},{%0,%1,%2,%3};\n"
        : "+f"(c[0]), "+f"(c[1]), "+f"(c[2]), "+f"(c[3])
        : "r"(a[0]), "r"(a[1]), "r"(a[2]), "r"(a[3]), "r"(b0), "r"(b1));
}

// ---------------- fp32 -> fp16 hi/lo split ----------------
__global__ void split16(const float4* __restrict__ in,
                        uint2* __restrict__ hi, uint2* __restrict__ lo, int n4)
{
    int i = blockIdx.x * 256 + threadIdx.x;
    if (i >= n4) return;
    float4 v = in[i];
    uint2 h, l;
    split2h(v.x, v.y, h.x, l.x);
    split2h(v.z, v.w, h.y, l.y);
    hi[i] = h; lo[i] = l;
}

// ---------------- GEMM: C = A @ W^T + bias (fp16 3-term emulated fp32) ----------------
// tile 128x64, kstep 32, 256 thr. mode: 0=fp32 out, 1=Q split, 2=K plain, 3=V split
__global__ __launch_bounds__(256) void gemm16(
    const __half* __restrict__ Ahi, const __half* __restrict__ Alo,
    const __half* __restrict__ Whi, const __half* __restrict__ Wlo,
    const float* __restrict__ bias, float* __restrict__ outF, int mode)
{
    __shared__ unsigned sAhi[128 * 20], sAlo[128 * 20];
    __shared__ unsigned sWhi[64 * 20],  sWlo[64 * 20];

    const int tid  = threadIdx.x;
    const int lane = tid & 31, warp = tid >> 5;
    const int wm = warp >> 1, wn = warp & 1;
    const int r = lane >> 2, c = lane & 3;
    const int m0 = blockIdx.y * 128, n0 = blockIdx.x * 64;

    const uint32_t* A32h = (const uint32_t*)Ahi;
    const uint32_t* A32l = (const uint32_t*)Alo;
    const uint32_t* W32h = (const uint32_t*)Whi;
    const uint32_t* W32l = (const uint32_t*)Wlo;

    float acc[2][4][4] = {};

    for (int k0 = 0; k0 < HID; k0 += 32) {
        #pragma unroll
        for (int j = 0; j < 8; j++) {
            int idx = tid + j * 256;               // 0..2047
            int row = idx >> 4, p = idx & 15;
            size_t ao = ((size_t)(m0 + row) * HID + k0) / 2 + p;
            sAhi[row * 20 + p] = A32h[ao];
            sAlo[row * 20 + p] = A32l[ao];
        }
        #pragma unroll
        for (int j = 0; j < 4; j++) {
            int idx = tid + j * 256;               // 0..1023
            int row = idx >> 4, p = idx & 15;
            size_t wo = ((size_t)(n0 + row) * HID + k0) / 2 + p;
            sWhi[row * 20 + p] = W32h[wo];
            sWlo[row * 20 + p] = W32l[wo];
        }
        __syncthreads();

        #pragma unroll
        for (int kk = 0; kk < 2; kk++) {
            unsigned ah[2][4], al[2][4];
            #pragma unroll
            for (int mt = 0; mt < 2; mt++) {
                int base = wm * 32 + mt * 16;
                ah[mt][0] = sAhi[(base + r)     * 20 + kk * 8 + c];
                ah[mt][1] = sAhi[(base + r + 8) * 20 + kk * 8 + c];
                ah[mt][2] = sAhi[(base + r)     * 20 + kk * 8 + c + 4];
                ah[mt][3] = sAhi[(base + r + 8) * 20 + kk * 8 + c + 4];
                al[mt][0] = sAlo[(base + r)     * 20 + kk * 8 + c];
                al[mt][1] = sAlo[(base + r + 8) * 20 + kk * 8 + c];
                al[mt][2] = sAlo[(base + r)     * 20 + kk * 8 + c + 4];
                al[mt][3] = sAlo[(base + r + 8) * 20 + kk * 8 + c + 4];
            }
            #pragma unroll
            for (int nt = 0; nt < 4; nt++) {
                int n = wn * 32 + nt * 8 + r;
                unsigned bh0 = sWhi[n * 20 + kk * 8 + c];
                unsigned bh1 = sWhi[n * 20 + kk * 8 + c + 4];
                unsigned bl0 = sWlo[n * 20 + kk * 8 + c];
                unsigned bl1 = sWlo[n * 20 + kk * 8 + c + 4];
                #pragma unroll
                for (int mt = 0; mt < 2; mt++) {
                    mma_h(acc[mt][nt], ah[mt], bh0, bh1);
                    mma_h(acc[mt][nt], al[mt], bh0, bh1);
                    mma_h(acc[mt][nt], ah[mt], bl0, bl1);
                }
            }
        }
        __syncthreads();
    }

    uint32_t* Qh32 = (uint32_t*)g_qh; uint32_t* Ql32 = (uint32_t*)g_ql;
    uint32_t* Kf32 = (uint32_t*)g_kf;
    uint32_t* Vh32 = (uint32_t*)g_vh; uint32_t* Vl32 = (uint32_t*)g_vl;

    #pragma unroll
    for (int mt = 0; mt < 2; mt++) {
        #pragma unroll
        for (int nt = 0; nt < 4; nt++) {
            int row = m0 + wm * 32 + mt * 16 + r;
            int col = n0 + wn * 32 + nt * 8 + 2 * c;
            float b0v = bias[col], b1v = bias[col + 1];
            float v00 = acc[mt][nt][0] + b0v;
            float v01 = acc[mt][nt][1] + b1v;
            float v10 = acc[mt][nt][2] + b0v;
            float v11 = acc[mt][nt][3] + b1v;
            if (mode == 0) {
                outF[(size_t)row * HID + col]           = v00;
                outF[(size_t)row * HID + col + 1]       = v01;
                outF[(size_t)(row + 8) * HID + col]     = v10;
                outF[(size_t)(row + 8) * HID + col + 1] = v11;
            } else {
                int hh = col >> 6, d = col & 63;
                int bb0 = row >> 11, s0 = row & (SEQ - 1);
                int bb1 = (row + 8) >> 11, s1 = (row + 8) & (SEQ - 1);
                size_t o0 = ((((size_t)(bb0 * NHEAD + hh)) * SEQ + s0) * HDIM + d) / 2;
                size_t o1 = ((((size_t)(bb1 * NHEAD + hh)) * SEQ + s1) * HDIM + d) / 2;
                if (mode == 1) {
                    split2h(v00, v01, Qh32[o0], Ql32[o0]);
                    split2h(v10, v11, Qh32[o1], Ql32[o1]);
                } else if (mode == 2) {
                    Kf32[o0] = pack2h(__float2half_rn(v00), __float2half_rn(v01));
                    Kf32[o1] = pack2h(__float2half_rn(v10), __float2half_rn(v11));
                } else {
                    split2h(v00, v01, Vh32[o0], Vl32[o0]);
                    split2h(v10, v11, Vh32[o1], Vl32[o1]);
                }
            }
        }
    }
}

// ---------------- V transpose: [bh][s][d] -> [bh][d][s] (hi & lo) ----------------
__global__ __launch_bounds__(256) void transV()
{
    __shared__ __half th[64][66], tl[64][66];
    const int tid = threadIdx.x;
    const int s0  = blockIdx.x * 64;
    const int bh  = blockIdx.y;

    const uint32_t* Vh32 = (const uint32_t*)g_vh + (size_t)bh * SEQ * 32;
    const uint32_t* Vl32 = (const uint32_t*)g_vl + (size_t)bh * SEQ * 32;
    uint32_t* Th32 = (uint32_t*)g_vth + (size_t)bh * HDIM * (SEQ / 2);
    uint32_t* Tl32 = (uint32_t*)g_vtl + (size_t)bh * HDIM * (SEQ / 2);

    #pragma unroll
    for (int j = 0; j < 8; j++) {
        int idx = tid + j * 256;
        int row = idx >> 5, p = idx & 31;
        *(uint32_t*)&th[row][2 * p] = Vh32[(size_t)(s0 + row) * 32 + p];
        *(uint32_t*)&tl[row][2 * p] = Vl32[(size_t)(s0 + row) * 32 + p];
    }
    __syncthreads();
    #pragma unroll
    for (int j = 0; j < 8; j++) {
        int idx = tid + j * 256;
        int d = idx >> 5, q = idx & 31;
        size_t off = (size_t)d * (SEQ / 2) + s0 / 2 + q;
        Th32[off] = pack2h(th[2 * q][d], th[2 * q + 1][d]);
        Tl32[off] = pack2h(tl[2 * q][d], tl[2 * q + 1][d]);
    }
}

// ---------------- fused attention (fp16 mma, fixed-max softmax) ----------------
// CTA: 128 q-rows of one (b,h), 8 warps x 16 q, 32 k-tiles of 64.
// S = (Qh+Ql) x Kf (2-term); PV = (Ph x Vh) + (Pl x Vh) + (Ph x Vl) (3-term).
__global__ __launch_bounds__(256) void attn16(const float* __restrict__ mask)
{
    extern __shared__ unsigned sm[];
    unsigned* sK  = sm;                 // 64*36
    unsigned* sVh = sK  + 64 * 36;      // 64*36  (V^T hi: [d][kv-pair])
    unsigned* sVl = sVh + 64 * 36;      // 64*36
    unsigned* sPh = sVl + 64 * 36;      // 128*36
    unsigned* sPl = sPh + 128 * 36;     // 128*36

    const int tid  = threadIdx.x;
    const int lane = tid & 31, warp = tid >> 5;
    const int r = lane >> 2, c = lane & 3;
    const int bh = blockIdx.y;
    const int bb = bh >> 4, h = bh & 15;
    const int q0 = blockIdx.x * 128;

    const uint32_t* Qh32 = (const uint32_t*)g_qh + (size_t)bh * SEQ * 32;
    const uint32_t* Ql32 = (const uint32_t*)g_ql + (size_t)bh * SEQ * 32;
    const uint32_t* Kf32 = (const uint32_t*)g_kf + (size_t)bh * SEQ * 32;
    const uint32_t* Th32 = (const uint32_t*)g_vth + (size_t)bh * HDIM * (SEQ / 2);
    const uint32_t* Tl32 = (const uint32_t*)g_vtl + (size_t)bh * HDIM * (SEQ / 2);

    // Q fragments (hi/lo), 16 q-rows per warp
    unsigned qh[4][4], ql[4][4];
    {
        int qr = q0 + warp * 16 + r;
        const uint32_t* rh0 = Qh32 + (size_t)qr * 32;
        const uint32_t* rh8 = Qh32 + (size_t)(qr + 8) * 32;
        const uint32_t* rl0 = Ql32 + (size_t)qr * 32;
        const uint32_t* rl8 = Ql32 + (size_t)(qr + 8) * 32;
        #pragma unroll
        for (int kk = 0; kk < 4; kk++) {
            qh[kk][0] = rh0[kk * 8 + c];     qh[kk][1] = rh8[kk * 8 + c];
            qh[kk][2] = rh0[kk * 8 + c + 4]; qh[kk][3] = rh8[kk * 8 + c + 4];
            ql[kk][0] = rl0[kk * 8 + c];     ql[kk][1] = rl8[kk * 8 + c];
            ql[kk][2] = rl0[kk * 8 + c + 4]; ql[kk][3] = rl8[kk * 8 + c + 4];
        }
    }

    float o[8][4] = {};
    float lsum_lo = 0.0f, lsum_hi = 0.0f;

    for (int kt = 0; kt < SEQ / 64; kt++) {
        const int k0 = kt * 64;

        // fill K (plain) + V^T (hi/lo): pure u32 copies, coalesced
        #pragma unroll
        for (int j = 0; j < 8; j++) {
            int idx = tid + j * 256;          // 0..2047
            int row = idx >> 5, p = idx & 31;
            sK [row * 36 + p] = Kf32[(size_t)(k0 + row) * 32 + p];
            sVh[row * 36 + p] = Th32[(size_t)row * (SEQ / 2) + k0 / 2 + p];
            sVl[row * 36 + p] = Tl32[(size_t)row * (SEQ / 2) + k0 / 2 + p];
        }
        __syncthreads();

        // S = Q K^T (2-term fp16)
        float s[8][4] = {};
        #pragma unroll
        for (int kk = 0; kk < 4; kk++) {
            #pragma unroll
            for (int nt = 0; nt < 8; nt++) {
                int n = nt * 8 + r;
                unsigned b0 = sK[n * 36 + kk * 8 + c];
                unsigned b1 = sK[n * 36 + kk * 8 + c + 4];
                mma_h(s[nt], qh[kk], b0, b1);
                mma_h(s[nt], ql[kk], b0, b1);
            }
        }

        // fixed-max softmax: p = exp(s/8 + mask); accumulate l; store P split fp16
        int prow = warp * 16 + r;
        #pragma unroll
        for (int nt = 0; nt < 8; nt++) {
            int col = k0 + nt * 8 + 2 * c;
            float mk0 = __ldg(mask + (size_t)bb * SEQ + col);
            float mk1 = __ldg(mask + (size_t)bb * SEQ + col + 1);
            float p0 = __expf(fmaf(s[nt][0], 0.125f, mk0));
            float p1 = __expf(fmaf(s[nt][1], 0.125f, mk1));
            float p2 = __expf(fmaf(s[nt][2], 0.125f, mk0));
            float p3 = __expf(fmaf(s[nt][3], 0.125f, mk1));
            lsum_lo += p0 + p1;
            lsum_hi += p2 + p3;
            split2h(p0, p1, sPh[prow * 36 + nt * 4 + c], sPl[prow * 36 + nt * 4 + c]);
            split2h(p2, p3, sPh[(prow + 8) * 36 + nt * 4 + c], sPl[(prow + 8) * 36 + nt * 4 + c]);
        }
        __syncwarp();

        // O += P V (3-term fp16)
        int pbase = warp * 16;
        #pragma unroll
        for (int kk = 0; kk < 4; kk++) {
            unsigned ah[4], al[4];
            ah[0] = sPh[(pbase + r)     * 36 + kk * 8 + c];
            ah[1] = sPh[(pbase + r + 8) * 36 + kk * 8 + c];
            ah[2] = sPh[(pbase + r)     * 36 + kk * 8 + c + 4];
            ah[3] = sPh[(pbase + r + 8) * 36 + kk * 8 + c + 4];
            al[0] = sPl[(pbase + r)     * 36 + kk * 8 + c];
            al[1] = sPl[(pbase + r + 8) * 36 + kk * 8 + c];
            al[2] = sPl[(pbase + r)     * 36 + kk * 8 + c + 4];
            al[3] = sPl[(pbase + r + 8) * 36 + kk * 8 + c + 4];
            #pragma unroll
            for (int nt = 0; nt < 8; nt++) {
                int d = nt * 8 + r;
                unsigned bh0 = sVh[d * 36 + kk * 8 + c];
                unsigned bh1 = sVh[d * 36 + kk * 8 + c + 4];
                unsigned bl0 = sVl[d * 36 + kk * 8 + c];
                unsigned bl1 = sVl[d * 36 + kk * 8 + c + 4];
                mma_h(o[nt], ah, bh0, bh1);
                mma_h(o[nt], al, bh0, bh1);
                mma_h(o[nt], ah, bl0, bl1);
            }
        }
        __syncthreads();
    }

    // reduce l across the quad (c=0..3 share the q-row)
    #pragma unroll
    for (int d = 1; d <= 2; d <<= 1) {
        lsum_lo += __shfl_xor_sync(0xffffffffu, lsum_lo, d);
        lsum_hi += __shfl_xor_sync(0xffffffffu, lsum_hi, d);
    }
    float inv_lo = 1.0f / lsum_lo;
    float inv_hi = 1.0f / lsum_hi;

    // write ctx directly as split fp16 [m][n]
    uint32_t* Ch = (uint32_t*)g_cxh;
    uint32_t* Cl = (uint32_t*)g_cxl;
    size_t mrow  = (size_t)bb * SEQ + q0 + warp * 16 + r;
    size_t mrow8 = mrow + 8;
    #pragma unroll
    for (int nt = 0; nt < 8; nt++) {
        int col = h * 64 + nt * 8 + 2 * c;
        split2h(o[nt][0] * inv_lo, o[nt][1] * inv_lo,
                Ch[(mrow  * HID + col) / 2], Cl[(mrow  * HID + col) / 2]);
        split2h(o[nt][2] * inv_hi, o[nt][3] * inv_hi,
                Ch[(mrow8 * HID + col) / 2], Cl[(mrow8 * HID + col) / 2]);
    }
}

// ---------------------------------------------------------------------------

extern "C" void kernel_launch(void* const* d_in, const int* in_sizes, int n_in,
                              void* d_out, int out_size)
{
    const float* hs   = (const float*)d_in[0];
    const float* mask = (const float*)d_in[1];
    const float* Wq   = (const float*)d_in[2];
    const float* bq   = (const float*)d_in[3];
    const float* Wk   = (const float*)d_in[4];
    const float* bk   = (const float*)d_in[5];
    const float* Wv   = (const float*)d_in[6];
    const float* bv   = (const float*)d_in[7];
    const float* Wo   = (const float*)d_in[8];
    const float* bo   = (const float*)d_in[9];
    float* out = (float*)d_out;

    __half *hsh, *hsl, *wh, *wl, *cxh, *cxl;
    cudaGetSymbolAddress((void**)&hsh, g_hsh);
    cudaGetSymbolAddress((void**)&hsl, g_hsl);
    cudaGetSymbolAddress((void**)&wh,  g_wh);
    cudaGetSymbolAddress((void**)&wl,  g_wl);
    cudaGetSymbolAddress((void**)&cxh, g_cxh);
    cudaGetSymbolAddress((void**)&cxl, g_cxl);

    const int attn_smem = (3 * 64 * 36 + 2 * 128 * 36) * (int)sizeof(unsigned); // 64,512 B
    cudaFuncSetAttribute(attn16, cudaFuncAttributeMaxDynamicSharedMemorySize, attn_smem);

    dim3 blk(256);
    const int nHS = MROWS * HID / 4;   // 1,048,576 float4
    const int nW  = HID * HID / 4;     // 262,144 float4

    // presplit inputs
    split16<<<nHS / 256, blk>>>((const float4*)hs, (uint2*)hsh, (uint2*)hsl, nHS);
    split16<<<nW / 256, blk>>>((const float4*)Wq, (uint2*)(wh + 0 * HID * HID), (uint2*)(wl + 0 * HID * HID), nW);
    split16<<<nW / 256, blk>>>((const float4*)Wk, (uint2*)(wh + 1 * HID * HID), (uint2*)(wl + 1 * HID * HID), nW);
    split16<<<nW / 256, blk>>>((const float4*)Wv, (uint2*)(wh + 2 * HID * HID), (uint2*)(wl + 2 * HID * HID), nW);
    split16<<<nW / 256, blk>>>((const float4*)Wo, (uint2*)(wh + 3 * HID * HID), (uint2*)(wl + 3 * HID * HID), nW);

    dim3 gG(HID / 64, MROWS / 128);    // (16, 32)
    gemm16<<<gG, blk>>>(hsh, hsl, wh + 0 * HID * HID, wl + 0 * HID * HID, bq, nullptr, 1);
    gemm16<<<gG, blk>>>(hsh, hsl, wh + 1 * HID * HID, wl + 1 * HID * HID, bk, nullptr, 2);
    gemm16<<<gG, blk>>>(hsh, hsl, wh + 2 * HID * HID, wl + 2 * HID * HID, bv, nullptr, 3);

    dim3 gT(SEQ / 64, BH);             // (32, 32)
    transV<<<gT, blk>>>();

    dim3 gA(SEQ / 128, BH);            // (16, 32)
    attn16<<<gA, blk, attn_smem>>>(mask);

    gemm16<<<gG, blk>>>(cxh, cxl, wh + 3 * HID * HID, wl + 3 * HID * HID, bo, out, 0);
}

// round 7
// speedup vs baseline: 1.0743x; 1.0312x over previous
#include <cuda_runtime.h>
#include <cuda_fp16.h>
#include <cstdint>

#define BATCH 2
#define SEQ   2048
#define HID   1024
#define NHEAD 16
#define HDIM  64
#define MROWS (BATCH*SEQ)   // 4096
#define BH    (BATCH*NHEAD) // 32

// ---------------- device scratch (allocation-free rule) ----------------
__device__ __half g_hsh[MROWS*HID], g_hsl[MROWS*HID];     // hidden states hi/lo
__device__ __half g_wh[4*HID*HID],  g_wl[4*HID*HID];      // Wq,Wk,Wv,Wo hi/lo
__device__ __half g_qh[BH*SEQ*HDIM], g_ql[BH*SEQ*HDIM];   // Q split  [bh][s][d]
__device__ __half g_kf[BH*SEQ*HDIM];                      // K plain  [bh][s][d]
__device__ __half g_vh[BH*SEQ*HDIM], g_vl[BH*SEQ*HDIM];   // V split  [bh][s][d]
__device__ __half g_vth[BH*HDIM*SEQ], g_vtl[BH*HDIM*SEQ]; // V^T split [bh][d][s]
__device__ __half g_cxh[MROWS*HID], g_cxl[MROWS*HID];     // ctx split [m][n]

// ---------------- helpers ----------------
__device__ __forceinline__ unsigned pack2h(__half a, __half b) {
    __half2 t(a, b);
    return *reinterpret_cast<unsigned*>(&t);
}
__device__ __forceinline__ void split2h(float x0, float x1, unsigned &hi, unsigned &lo) {
    __half h0 = __float2half_rn(x0);
    __half h1 = __float2half_rn(x1);
    __half l0 = __float2half_rn(x0 - __half2float(h0));
    __half l1 = __float2half_rn(x1 - __half2float(h1));
    hi = pack2h(h0, h1); lo = pack2h(l0, l1);
}
__device__ __forceinline__ void mma_h(float* c, const unsigned* a,
                                      unsigned b0, unsigned b1) {
    asm volatile(
        "mma.sync.aligned.m16n8k16.row.col.f32.f16.f16.f32 "
        "{%0,%1,%2,%3},{%4,%5,%6,%7},{%8,%9},{%0,%1,%2,%3};\n"
        : "+f"(c[0]), "+f"(c[1]), "+f"(c[2]), "+f"(c[3])
        : "r"(a[0]), "r"(a[1]), "r"(a[2]), "r"(a[3]), "r"(b0), "r"(b1));
}

// ---------------- fp32 -> fp16 hi/lo split ----------------
__global__ void split16(const float4* __restrict__ in,
                        uint2* __restrict__ hi, uint2* __restrict__ lo, int n4)
{
    int i = blockIdx.x * 256 + threadIdx.x;
    if (i >= n4) return;
    float4 v = in[i];
    uint2 h, l;
    split2h(v.x, v.y, h.x, l.x);
    split2h(v.z, v.w, h.y, l.y);
    hi[i] = h; lo[i] = l;
}

// ---------------- GEMM: C = A @ W^T + bias (fp16 3-term emulated fp32) ----------------
// tile 128x64, kstep 32, 256 thr. mode: 0=fp32 out, 1=Q split, 2=K plain, 3=V split
__global__ __launch_bounds__(256) void gemm16(
    const __half* __restrict__ Ahi, const __half* __restrict__ Alo,
    const __half* __restrict__ Whi, const __half* __restrict__ Wlo,
    const float* __restrict__ bias, float* __restrict__ outF, int mode)
{
    __shared__ unsigned sAhi[128 * 20], sAlo[128 * 20];
    __shared__ unsigned sWhi[64 * 20],  sWlo[64 * 20];

    const int tid  = threadIdx.x;
    const int lane = tid & 31, warp = tid >> 5;
    const int wm = warp >> 1, wn = warp & 1;
    const int r = lane >> 2, c = lane & 3;
    const int m0 = blockIdx.y * 128, n0 = blockIdx.x * 64;

    const uint32_t* A32h = (const uint32_t*)Ahi;
    const uint32_t* A32l = (const uint32_t*)Alo;
    const uint32_t* W32h = (const uint32_t*)Whi;
    const uint32_t* W32l = (const uint32_t*)Wlo;

    float acc[2][4][4] = {};

    for (int k0 = 0; k0 < HID; k0 += 32) {
        #pragma unroll
        for (int j = 0; j < 8; j++) {
            int idx = tid + j * 256;               // 0..2047
            int row = idx >> 4, p = idx & 15;
            size_t ao = ((size_t)(m0 + row) * HID + k0) / 2 + p;
            sAhi[row * 20 + p] = A32h[ao];
            sAlo[row * 20 + p] = A32l[ao];
        }
        #pragma unroll
        for (int j = 0; j < 4; j++) {
            int idx = tid + j * 256;               // 0..1023
            int row = idx >> 4, p = idx & 15;
            size_t wo = ((size_t)(n0 + row) * HID + k0) / 2 + p;
            sWhi[row * 20 + p] = W32h[wo];
            sWlo[row * 20 + p] = W32l[wo];
        }
        __syncthreads();

        #pragma unroll
        for (int kk = 0; kk < 2; kk++) {
            unsigned ah[2][4], al[2][4];
            #pragma unroll
            for (int mt = 0; mt < 2; mt++) {
                int base = wm * 32 + mt * 16;
                ah[mt][0] = sAhi[(base + r)     * 20 + kk * 8 + c];
                ah[mt][1] = sAhi[(base + r + 8) * 20 + kk * 8 + c];
                ah[mt][2] = sAhi[(base + r)     * 20 + kk * 8 + c + 4];
                ah[mt][3] = sAhi[(base + r + 8) * 20 + kk * 8 + c + 4];
                al[mt][0] = sAlo[(base + r)     * 20 + kk * 8 + c];
                al[mt][1] = sAlo[(base + r + 8) * 20 + kk * 8 + c];
                al[mt][2] = sAlo[(base + r)     * 20 + kk * 8 + c + 4];
                al[mt][3] = sAlo[(base + r + 8) * 20 + kk * 8 + c + 4];
            }
            #pragma unroll
            for (int nt = 0; nt < 4; nt++) {
                int n = wn * 32 + nt * 8 + r;
                unsigned bh0 = sWhi[n * 20 + kk * 8 + c];
                unsigned bh1 = sWhi[n * 20 + kk * 8 + c + 4];
                unsigned bl0 = sWlo[n * 20 + kk * 8 + c];
                unsigned bl1 = sWlo[n * 20 + kk * 8 + c + 4];
                #pragma unroll
                for (int mt = 0; mt < 2; mt++) {
                    mma_h(acc[mt][nt], ah[mt], bh0, bh1);
                    mma_h(acc[mt][nt], al[mt], bh0, bh1);
                    mma_h(acc[mt][nt], ah[mt], bl0, bl1);
                }
            }
        }
        __syncthreads();
    }

    uint32_t* Qh32 = (uint32_t*)g_qh; uint32_t* Ql32 = (uint32_t*)g_ql;
    uint32_t* Kf32 = (uint32_t*)g_kf;
    uint32_t* Vh32 = (uint32_t*)g_vh; uint32_t* Vl32 = (uint32_t*)g_vl;

    #pragma unroll
    for (int mt = 0; mt < 2; mt++) {
        #pragma unroll
        for (int nt = 0; nt < 4; nt++) {
            int row = m0 + wm * 32 + mt * 16 + r;
            int col = n0 + wn * 32 + nt * 8 + 2 * c;
            float b0v = bias[col], b1v = bias[col + 1];
            float v00 = acc[mt][nt][0] + b0v;
            float v01 = acc[mt][nt][1] + b1v;
            float v10 = acc[mt][nt][2] + b0v;
            float v11 = acc[mt][nt][3] + b1v;
            if (mode == 0) {
                outF[(size_t)row * HID + col]           = v00;
                outF[(size_t)row * HID + col + 1]       = v01;
                outF[(size_t)(row + 8) * HID + col]     = v10;
                outF[(size_t)(row + 8) * HID + col + 1] = v11;
            } else {
                int hh = col >> 6, d = col & 63;
                int bb0 = row >> 11, s0 = row & (SEQ - 1);
                int bb1 = (row + 8) >> 11, s1 = (row + 8) & (SEQ - 1);
                size_t o0 = ((((size_t)(bb0 * NHEAD + hh)) * SEQ + s0) * HDIM + d) / 2;
                size_t o1 = ((((size_t)(bb1 * NHEAD + hh)) * SEQ + s1) * HDIM + d) / 2;
                if (mode == 1) {
                    split2h(v00, v01, Qh32[o0], Ql32[o0]);
                    split2h(v10, v11, Qh32[o1], Ql32[o1]);
                } else if (mode == 2) {
                    Kf32[o0] = pack2h(__float2half_rn(v00), __float2half_rn(v01));
                    Kf32[o1] = pack2h(__float2half_rn(v10), __float2half_rn(v11));
                } else {
                    split2h(v00, v01, Vh32[o0], Vl32[o0]);
                    split2h(v10, v11, Vh32[o1], Vl32[o1]);
                }
            }
        }
    }
}

// ---------------- V transpose: [bh][s][d] -> [bh][d][s] (hi & lo) ----------------
__global__ __launch_bounds__(256) void transV()
{
    __shared__ __half th[64][66], tl[64][66];
    const int tid = threadIdx.x;
    const int s0  = blockIdx.x * 64;
    const int bh  = blockIdx.y;

    const uint32_t* Vh32 = (const uint32_t*)g_vh + (size_t)bh * SEQ * 32;
    const uint32_t* Vl32 = (const uint32_t*)g_vl + (size_t)bh * SEQ * 32;
    uint32_t* Th32 = (uint32_t*)g_vth + (size_t)bh * HDIM * (SEQ / 2);
    uint32_t* Tl32 = (uint32_t*)g_vtl + (size_t)bh * HDIM * (SEQ / 2);

    #pragma unroll
    for (int j = 0; j < 8; j++) {
        int idx = tid + j * 256;
        int row = idx >> 5, p = idx & 31;
        *(uint32_t*)&th[row][2 * p] = Vh32[(size_t)(s0 + row) * 32 + p];
        *(uint32_t*)&tl[row][2 * p] = Vl32[(size_t)(s0 + row) * 32 + p];
    }
    __syncthreads();
    #pragma unroll
    for (int j = 0; j < 8; j++) {
        int idx = tid + j * 256;
        int d = idx >> 5, q = idx & 31;
        size_t off = (size_t)d * (SEQ / 2) + s0 / 2 + q;
        Th32[off] = pack2h(th[2 * q][d], th[2 * q + 1][d]);
        Tl32[off] = pack2h(tl[2 * q][d], tl[2 * q + 1][d]);
    }
}

// ---------------- fused attention (FA2 register pipeline) ----------------
// CTA: 128 q-rows of one (b,h), 8 warps x 16 q, 32 k-tiles of 64.
// S = (Qh+Ql) x Kf (2-term). P stays in registers (C-frag == A-frag layout).
// PV = Ph x Vh + Pl x Vh + Ph x Vl (3-term). Fixed-max softmax.
__global__ __launch_bounds__(256) void attn16(const float* __restrict__ mask)
{
    __shared__ unsigned sK [64 * 36];   // K plain  [kcol][dpair]
    __shared__ unsigned sVh[64 * 36];   // V^T hi   [d][kvpair]
    __shared__ unsigned sVl[64 * 36];   // V^T lo   [d][kvpair]

    const int tid  = threadIdx.x;
    const int lane = tid & 31, warp = tid >> 5;
    const int r = lane >> 2, c = lane & 3;
    const int bh = blockIdx.y;
    const int bb = bh >> 4, h = bh & 15;
    const int q0 = blockIdx.x * 128;

    const uint32_t* Qh32 = (const uint32_t*)g_qh + (size_t)bh * SEQ * 32;
    const uint32_t* Ql32 = (const uint32_t*)g_ql + (size_t)bh * SEQ * 32;
    const uint32_t* Kf32 = (const uint32_t*)g_kf + (size_t)bh * SEQ * 32;
    const uint32_t* Th32 = (const uint32_t*)g_vth + (size_t)bh * HDIM * (SEQ / 2);
    const uint32_t* Tl32 = (const uint32_t*)g_vtl + (size_t)bh * HDIM * (SEQ / 2);

    // Q fragments (hi/lo), 16 q-rows per warp, held in registers
    unsigned qh[4][4], ql[4][4];
    {
        int qr = q0 + warp * 16 + r;
        const uint32_t* rh0 = Qh32 + (size_t)qr * 32;
        const uint32_t* rh8 = Qh32 + (size_t)(qr + 8) * 32;
        const uint32_t* rl0 = Ql32 + (size_t)qr * 32;
        const uint32_t* rl8 = Ql32 + (size_t)(qr + 8) * 32;
        #pragma unroll
        for (int kk = 0; kk < 4; kk++) {
            qh[kk][0] = rh0[kk * 8 + c];     qh[kk][1] = rh8[kk * 8 + c];
            qh[kk][2] = rh0[kk * 8 + c + 4]; qh[kk][3] = rh8[kk * 8 + c + 4];
            ql[kk][0] = rl0[kk * 8 + c];     ql[kk][1] = rl8[kk * 8 + c];
            ql[kk][2] = rl0[kk * 8 + c + 4]; ql[kk][3] = rl8[kk * 8 + c + 4];
        }
    }

    float o[8][4] = {};
    float lsum_lo = 0.0f, lsum_hi = 0.0f;

    for (int kt = 0; kt < SEQ / 64; kt++) {
        const int k0 = kt * 64;

        // fill K + V^T: pure u32 copies, coalesced
        #pragma unroll
        for (int j = 0; j < 8; j++) {
            int idx = tid + j * 256;          // 0..2047
            int row = idx >> 5, p = idx & 31;
            sK [row * 36 + p] = Kf32[(size_t)(k0 + row) * 32 + p];
            sVh[row * 36 + p] = Th32[(size_t)row * (SEQ / 2) + k0 / 2 + p];
            sVl[row * 36 + p] = Tl32[(size_t)row * (SEQ / 2) + k0 / 2 + p];
        }
        __syncthreads();

        // S = Q K^T (2-term fp16)
        float s[8][4] = {};
        #pragma unroll
        for (int kk = 0; kk < 4; kk++) {
            #pragma unroll
            for (int nt = 0; nt < 8; nt++) {
                int n = nt * 8 + r;
                unsigned b0 = sK[n * 36 + kk * 8 + c];
                unsigned b1 = sK[n * 36 + kk * 8 + c + 4];
                mma_h(s[nt], qh[kk], b0, b1);
                mma_h(s[nt], ql[kk], b0, b1);
            }
        }

        // fixed-max softmax: p = exp(s/8 + mask); accumulate l (in registers)
        #pragma unroll
        for (int nt = 0; nt < 8; nt++) {
            int col = k0 + nt * 8 + 2 * c;
            float mk0 = __ldg(mask + (size_t)bb * SEQ + col);
            float mk1 = __ldg(mask + (size_t)bb * SEQ + col + 1);
            s[nt][0] = __expf(fmaf(s[nt][0], 0.125f, mk0));
            s[nt][1] = __expf(fmaf(s[nt][1], 0.125f, mk1));
            s[nt][2] = __expf(fmaf(s[nt][2], 0.125f, mk0));
            s[nt][3] = __expf(fmaf(s[nt][3], 0.125f, mk1));
            lsum_lo += s[nt][0] + s[nt][1];
            lsum_hi += s[nt][2] + s[nt][3];
        }

        // P: C-fragment layout == A-fragment layout for PV mma. Split in regs.
        unsigned aPh[4][4], aPl[4][4];
        #pragma unroll
        for (int kk = 0; kk < 4; kk++) {
            split2h(s[2*kk][0],   s[2*kk][1],   aPh[kk][0], aPl[kk][0]);
            split2h(s[2*kk][2],   s[2*kk][3],   aPh[kk][1], aPl[kk][1]);
            split2h(s[2*kk+1][0], s[2*kk+1][1], aPh[kk][2], aPl[kk][2]);
            split2h(s[2*kk+1][2], s[2*kk+1][3], aPh[kk][3], aPl[kk][3]);
        }

        // O += P V (3-term fp16), B from smem V^T
        #pragma unroll
        for (int kk = 0; kk < 4; kk++) {
            #pragma unroll
            for (int nt = 0; nt < 8; nt++) {
                int d = nt * 8 + r;
                unsigned bh0 = sVh[d * 36 + kk * 8 + c];
                unsigned bh1 = sVh[d * 36 + kk * 8 + c + 4];
                unsigned bl0 = sVl[d * 36 + kk * 8 + c];
                unsigned bl1 = sVl[d * 36 + kk * 8 + c + 4];
                mma_h(o[nt], aPh[kk], bh0, bh1);
                mma_h(o[nt], aPl[kk], bh0, bh1);
                mma_h(o[nt], aPh[kk], bl0, bl1);
            }
        }
        __syncthreads();
    }

    // reduce l across the quad (c=0..3 share the q-row)
    #pragma unroll
    for (int d = 1; d <= 2; d <<= 1) {
        lsum_lo += __shfl_xor_sync(0xffffffffu, lsum_lo, d);
        lsum_hi += __shfl_xor_sync(0xffffffffu, lsum_hi, d);
    }
    float inv_lo = 1.0f / lsum_lo;
    float inv_hi = 1.0f / lsum_hi;

    // write ctx directly as split fp16 [m][n]
    uint32_t* Ch = (uint32_t*)g_cxh;
    uint32_t* Cl = (uint32_t*)g_cxl;
    size_t mrow  = (size_t)bb * SEQ + q0 + warp * 16 + r;
    size_t mrow8 = mrow + 8;
    #pragma unroll
    for (int nt = 0; nt < 8; nt++) {
        int col = h * 64 + nt * 8 + 2 * c;
        split2h(o[nt][0] * inv_lo, o[nt][1] * inv_lo,
                Ch[(mrow  * HID + col) / 2], Cl[(mrow  * HID + col) / 2]);
        split2h(o[nt][2] * inv_hi, o[nt][3] * inv_hi,
                Ch[(mrow8 * HID + col) / 2], Cl[(mrow8 * HID + col) / 2]);
    }
}

// ---------------------------------------------------------------------------

extern "C" void kernel_launch(void* const* d_in, const int* in_sizes, int n_in,
                              void* d_out, int out_size)
{
    const float* hs   = (const float*)d_in[0];
    const float* mask = (const float*)d_in[1];
    const float* Wq   = (const float*)d_in[2];
    const float* bq   = (const float*)d_in[3];
    const float* Wk   = (const float*)d_in[4];
    const float* bk   = (const float*)d_in[5];
    const float* Wv   = (const float*)d_in[6];
    const float* bv   = (const float*)d_in[7];
    const float* Wo   = (const float*)d_in[8];
    const float* bo   = (const float*)d_in[9];
    float* out = (float*)d_out;

    __half *hsh, *hsl, *wh, *wl, *cxh, *cxl;
    cudaGetSymbolAddress((void**)&hsh, g_hsh);
    cudaGetSymbolAddress((void**)&hsl, g_hsl);
    cudaGetSymbolAddress((void**)&wh,  g_wh);
    cudaGetSymbolAddress((void**)&wl,  g_wl);
    cudaGetSymbolAddress((void**)&cxh, g_cxh);
    cudaGetSymbolAddress((void**)&cxl, g_cxl);

    dim3 blk(256);
    const int nHS = MROWS * HID / 4;   // 1,048,576 float4
    const int nW  = HID * HID / 4;     // 262,144 float4

    // presplit inputs
    split16<<<nHS / 256, blk>>>((const float4*)hs, (uint2*)hsh, (uint2*)hsl, nHS);
    split16<<<nW / 256, blk>>>((const float4*)Wq, (uint2*)(wh + 0 * HID * HID), (uint2*)(wl + 0 * HID * HID), nW);
    split16<<<nW / 256, blk>>>((const float4*)Wk, (uint2*)(wh + 1 * HID * HID), (uint2*)(wl + 1 * HID * HID), nW);
    split16<<<nW / 256, blk>>>((const float4*)Wv, (uint2*)(wh + 2 * HID * HID), (uint2*)(wl + 2 * HID * HID), nW);
    split16<<<nW / 256, blk>>>((const float4*)Wo, (uint2*)(wh + 3 * HID * HID), (uint2*)(wl + 3 * HID * HID), nW);

    dim3 gG(HID / 64, MROWS / 128);    // (16, 32)
    gemm16<<<gG, blk>>>(hsh, hsl, wh + 0 * HID * HID, wl + 0 * HID * HID, bq, nullptr, 1);
    gemm16<<<gG, blk>>>(hsh, hsl, wh + 1 * HID * HID, wl + 1 * HID * HID, bk, nullptr, 2);
    gemm16<<<gG, blk>>>(hsh, hsl, wh + 2 * HID * HID, wl + 2 * HID * HID, bv, nullptr, 3);

    dim3 gT(SEQ / 64, BH);             // (32, 32)
    transV<<<gT, blk>>>();

    dim3 gA(SEQ / 128, BH);            // (16, 32)
    attn16<<<gA, blk>>>(mask);

    gemm16<<<gG, blk>>>(cxh, cxl, wh + 3 * HID * HID, wl + 3 * HID * HID, bo, out, 0);
}

// round 8
// speedup vs baseline: 1.3620x; 1.2678x over previous
#include <cuda_runtime.h>
#include <cuda_fp16.h>
#include <cstdint>

#define BATCH 2
#define SEQ   2048
#define HID   1024
#define NHEAD 16
#define HDIM  64
#define MROWS (BATCH*SEQ)   // 4096
#define BH    (BATCH*NHEAD) // 32

// ---------------- device scratch (allocation-free rule) ----------------
__device__ __half g_hsh[MROWS*HID], g_hsl[MROWS*HID];     // hidden states hi/lo
__device__ __half g_wh[4*HID*HID],  g_wl[4*HID*HID];      // Wq,Wk,Wv,Wo hi/lo
__device__ __half g_qh[BH*SEQ*HDIM], g_ql[BH*SEQ*HDIM];   // Q split  [bh][s][d]
__device__ __half g_kf[BH*SEQ*HDIM];                      // K plain  [bh][s][d]
__device__ __half g_vh[BH*SEQ*HDIM], g_vl[BH*SEQ*HDIM];   // V split  [bh][s][d]
__device__ __half g_vth[BH*HDIM*SEQ], g_vtl[BH*HDIM*SEQ]; // V^T split [bh][d][s]
__device__ __half g_cxh[MROWS*HID], g_cxl[MROWS*HID];     // ctx split [m][n]

// ---------------- helpers ----------------
__device__ __forceinline__ unsigned pack2h(__half a, __half b) {
    __half2 t(a, b);
    return *reinterpret_cast<unsigned*>(&t);
}
__device__ __forceinline__ void split2h(float x0, float x1, unsigned &hi, unsigned &lo) {
    __half h0 = __float2half_rn(x0);
    __half h1 = __float2half_rn(x1);
    __half l0 = __float2half_rn(x0 - __half2float(h0));
    __half l1 = __float2half_rn(x1 - __half2float(h1));
    hi = pack2h(h0, h1); lo = pack2h(l0, l1);
}
__device__ __forceinline__ void mma_h(float* c, const unsigned* a,
                                      unsigned b0, unsigned b1) {
    asm volatile(
        "mma.sync.aligned.m16n8k16.row.col.f32.f16.f16.f32 "
        "{%0,%1,%2,%3},{%4,%5,%6,%7},{%8,%9},{%0,%1,%2,%3};\n"
        : "+f"(c[0]), "+f"(c[1]), "+f"(c[2]), "+f"(c[3])
        : "r"(a[0]), "r"(a[1]), "r"(a[2]), "r"(a[3]), "r"(b0), "r"(b1));
}
__device__ __forceinline__ uint32_t s2u(const void* p) {
    uint32_t a;
    asm("{ .reg .u64 t; cvta.to.shared.u64 t, %1; cvt.u32.u64 %0, t; }" : "=r"(a) : "l"(p));
    return a;
}
__device__ __forceinline__ void cp16(uint32_t saddr, const void* gaddr) {
    asm volatile("cp.async.cg.shared.global [%0], [%1], 16;" :: "r"(saddr), "l"(gaddr));
}
#define CP_COMMIT() asm volatile("cp.async.commit_group;" ::: "memory")
#define CP_WAIT1()  asm volatile("cp.async.wait_group 1;" ::: "memory")

// ---------------- fp32 -> fp16 hi/lo split ----------------
__global__ void split16(const float4* __restrict__ in,
                        uint2* __restrict__ hi, uint2* __restrict__ lo, int n4)
{
    int i = blockIdx.x * 256 + threadIdx.x;
    if (i >= n4) return;
    float4 v = in[i];
    uint2 h, l;
    split2h(v.x, v.y, h.x, l.x);
    split2h(v.z, v.w, h.y, l.y);
    hi[i] = h; lo[i] = l;
}

// ---------------- GEMM: C = A @ W^T + bias (fp16 3-term, cp.async 3-stage) ----------------
// tile 128x64, kstep 32 halves (=16 u32). Stage stride 7680 u32:
//   AH @ 0 (128x20), AL @ 2560, WH @ 5120 (64x20), WL @ 6400.
// mode: 0=fp32 out, 1=Q split, 2=K plain, 3=V split
__global__ __launch_bounds__(256, 2) void gemm16(
    const __half* __restrict__ Ahi, const __half* __restrict__ Alo,
    const __half* __restrict__ Whi, const __half* __restrict__ Wlo,
    const float* __restrict__ bias, float* __restrict__ outF, int mode)
{
    extern __shared__ unsigned sm[];

    const int tid  = threadIdx.x;
    const int lane = tid & 31, warp = tid >> 5;
    const int wm = warp >> 1, wn = warp & 1;
    const int r = lane >> 2, c = lane & 3;
    const int m0 = blockIdx.y * 128, n0 = blockIdx.x * 64;

    const uint32_t* A32h = (const uint32_t*)Ahi;
    const uint32_t* A32l = (const uint32_t*)Alo;
    const uint32_t* W32h = (const uint32_t*)Whi;
    const uint32_t* W32l = (const uint32_t*)Wlo;

    const uint32_t smbase = s2u(sm);

    // issue one chunk's loads into stage st (6 x cp16 per thread)
    auto gload = [&](int kc, int st) {
        uint32_t base = smbase + (uint32_t)st * 7680u * 4u;
        #pragma unroll
        for (int j = 0; j < 2; j++) {
            int idx = tid + j * 256;             // 0..511
            int row = idx >> 2, v = idx & 3;
            size_t go = (size_t)(m0 + row) * 512 + kc * 16 + v * 4;
            uint32_t so = (uint32_t)(row * 20 + v * 4) * 4u;
            cp16(base + so,             A32h + go);
            cp16(base + 2560u*4u + so,  A32l + go);
        }
        {
            int row = tid >> 2, v = tid & 3;
            size_t go = (size_t)(n0 + row) * 512 + kc * 16 + v * 4;
            uint32_t so = (uint32_t)(row * 20 + v * 4) * 4u;
            cp16(base + 5120u*4u + so,  W32h + go);
            cp16(base + 6400u*4u + so,  W32l + go);
        }
    };

    float acc[2][4][4] = {};

    gload(0, 0); CP_COMMIT();
    gload(1, 1); CP_COMMIT();

    for (int kc = 0; kc < 32; kc++) {
        CP_WAIT1();
        __syncthreads();
        if (kc + 2 < 32) gload(kc + 2, (kc + 2) % 3);
        CP_COMMIT();

        unsigned* st   = sm + (kc % 3) * 7680;
        unsigned* sAhi = st;
        unsigned* sAlo = st + 2560;
        unsigned* sWhi = st + 5120;
        unsigned* sWlo = st + 6400;

        #pragma unroll
        for (int kk = 0; kk < 2; kk++) {
            unsigned ah[2][4], al[2][4];
            #pragma unroll
            for (int mt = 0; mt < 2; mt++) {
                int base = wm * 32 + mt * 16;
                ah[mt][0] = sAhi[(base + r)     * 20 + kk * 8 + c];
                ah[mt][1] = sAhi[(base + r + 8) * 20 + kk * 8 + c];
                ah[mt][2] = sAhi[(base + r)     * 20 + kk * 8 + c + 4];
                ah[mt][3] = sAhi[(base + r + 8) * 20 + kk * 8 + c + 4];
                al[mt][0] = sAlo[(base + r)     * 20 + kk * 8 + c];
                al[mt][1] = sAlo[(base + r + 8) * 20 + kk * 8 + c];
                al[mt][2] = sAlo[(base + r)     * 20 + kk * 8 + c + 4];
                al[mt][3] = sAlo[(base + r + 8) * 20 + kk * 8 + c + 4];
            }
            #pragma unroll
            for (int nt = 0; nt < 4; nt++) {
                int n = wn * 32 + nt * 8 + r;
                unsigned bh0 = sWhi[n * 20 + kk * 8 + c];
                unsigned bh1 = sWhi[n * 20 + kk * 8 + c + 4];
                unsigned bl0 = sWlo[n * 20 + kk * 8 + c];
                unsigned bl1 = sWlo[n * 20 + kk * 8 + c + 4];
                #pragma unroll
                for (int mt = 0; mt < 2; mt++) {
                    mma_h(acc[mt][nt], ah[mt], bh0, bh1);
                    mma_h(acc[mt][nt], al[mt], bh0, bh1);
                    mma_h(acc[mt][nt], ah[mt], bl0, bl1);
                }
            }
        }
    }

    uint32_t* Qh32 = (uint32_t*)g_qh; uint32_t* Ql32 = (uint32_t*)g_ql;
    uint32_t* Kf32 = (uint32_t*)g_kf;
    uint32_t* Vh32 = (uint32_t*)g_vh; uint32_t* Vl32 = (uint32_t*)g_vl;

    #pragma unroll
    for (int mt = 0; mt < 2; mt++) {
        #pragma unroll
        for (int nt = 0; nt < 4; nt++) {
            int row = m0 + wm * 32 + mt * 16 + r;
            int col = n0 + wn * 32 + nt * 8 + 2 * c;
            float b0v = bias[col], b1v = bias[col + 1];
            float v00 = acc[mt][nt][0] + b0v;
            float v01 = acc[mt][nt][1] + b1v;
            float v10 = acc[mt][nt][2] + b0v;
            float v11 = acc[mt][nt][3] + b1v;
            if (mode == 0) {
                outF[(size_t)row * HID + col]           = v00;
                outF[(size_t)row * HID + col + 1]       = v01;
                outF[(size_t)(row + 8) * HID + col]     = v10;
                outF[(size_t)(row + 8) * HID + col + 1] = v11;
            } else {
                int hh = col >> 6, d = col & 63;
                int bb0 = row >> 11, s0 = row & (SEQ - 1);
                int bb1 = (row + 8) >> 11, s1 = (row + 8) & (SEQ - 1);
                size_t o0 = ((((size_t)(bb0 * NHEAD + hh)) * SEQ + s0) * HDIM + d) / 2;
                size_t o1 = ((((size_t)(bb1 * NHEAD + hh)) * SEQ + s1) * HDIM + d) / 2;
                if (mode == 1) {
                    split2h(v00, v01, Qh32[o0], Ql32[o0]);
                    split2h(v10, v11, Qh32[o1], Ql32[o1]);
                } else if (mode == 2) {
                    Kf32[o0] = pack2h(__float2half_rn(v00), __float2half_rn(v01));
                    Kf32[o1] = pack2h(__float2half_rn(v10), __float2half_rn(v11));
                } else {
                    split2h(v00, v01, Vh32[o0], Vl32[o0]);
                    split2h(v10, v11, Vh32[o1], Vl32[o1]);
                }
            }
        }
    }
}

// ---------------- V transpose: [bh][s][d] -> [bh][d][s] (hi & lo) ----------------
__global__ __launch_bounds__(256) void transV()
{
    __shared__ __half th[64][66], tl[64][66];
    const int tid = threadIdx.x;
    const int s0  = blockIdx.x * 64;
    const int bh  = blockIdx.y;

    const uint32_t* Vh32 = (const uint32_t*)g_vh + (size_t)bh * SEQ * 32;
    const uint32_t* Vl32 = (const uint32_t*)g_vl + (size_t)bh * SEQ * 32;
    uint32_t* Th32 = (uint32_t*)g_vth + (size_t)bh * HDIM * (SEQ / 2);
    uint32_t* Tl32 = (uint32_t*)g_vtl + (size_t)bh * HDIM * (SEQ / 2);

    #pragma unroll
    for (int j = 0; j < 8; j++) {
        int idx = tid + j * 256;
        int row = idx >> 5, p = idx & 31;
        *(uint32_t*)&th[row][2 * p] = Vh32[(size_t)(s0 + row) * 32 + p];
        *(uint32_t*)&tl[row][2 * p] = Vl32[(size_t)(s0 + row) * 32 + p];
    }
    __syncthreads();
    #pragma unroll
    for (int j = 0; j < 8; j++) {
        int idx = tid + j * 256;
        int d = idx >> 5, q = idx & 31;
        size_t off = (size_t)d * (SEQ / 2) + s0 / 2 + q;
        Th32[off] = pack2h(th[2 * q][d], th[2 * q + 1][d]);
        Tl32[off] = pack2h(tl[2 * q][d], tl[2 * q + 1][d]);
    }
}

// ---------------- fused attention (FA2 regs + cp.async 3-stage) ----------------
// CTA: 128 q-rows of one (b,h), 8 warps x 16 q, 32 k-tiles of 64.
// Stage stride 6912 u32: K @ 0 (64x36), Vh @ 2304, Vl @ 4608.
__global__ __launch_bounds__(256, 2) void attn16(const float* __restrict__ mask)
{
    extern __shared__ unsigned sm[];

    const int tid  = threadIdx.x;
    const int lane = tid & 31, warp = tid >> 5;
    const int r = lane >> 2, c = lane & 3;
    const int bh = blockIdx.y;
    const int bb = bh >> 4, h = bh & 15;
    const int q0 = blockIdx.x * 128;

    const uint32_t* Qh32 = (const uint32_t*)g_qh + (size_t)bh * SEQ * 32;
    const uint32_t* Ql32 = (const uint32_t*)g_ql + (size_t)bh * SEQ * 32;
    const uint32_t* Kf32 = (const uint32_t*)g_kf + (size_t)bh * SEQ * 32;
    const uint32_t* Th32 = (const uint32_t*)g_vth + (size_t)bh * HDIM * (SEQ / 2);
    const uint32_t* Tl32 = (const uint32_t*)g_vtl + (size_t)bh * HDIM * (SEQ / 2);

    const uint32_t smbase = s2u(sm);

    auto aload = [&](int kt, int st) {
        uint32_t base = smbase + (uint32_t)st * 6912u * 4u;
        const int k0 = kt * 64;
        #pragma unroll
        for (int j = 0; j < 2; j++) {
            int idx = tid + j * 256;             // 0..511
            int row = idx >> 3, v = idx & 7;
            uint32_t so = (uint32_t)(row * 36 + v * 4) * 4u;
            cp16(base + so,            Kf32 + (size_t)(k0 + row) * 32 + v * 4);
            cp16(base + 2304u*4u + so, Th32 + (size_t)row * (SEQ / 2) + k0 / 2 + v * 4);
            cp16(base + 4608u*4u + so, Tl32 + (size_t)row * (SEQ / 2) + k0 / 2 + v * 4);
        }
    };

    // Q fragments (hi/lo), 16 q-rows per warp, held in registers
    unsigned qh[4][4], ql[4][4];
    {
        int qr = q0 + warp * 16 + r;
        const uint32_t* rh0 = Qh32 + (size_t)qr * 32;
        const uint32_t* rh8 = Qh32 + (size_t)(qr + 8) * 32;
        const uint32_t* rl0 = Ql32 + (size_t)qr * 32;
        const uint32_t* rl8 = Ql32 + (size_t)(qr + 8) * 32;
        #pragma unroll
        for (int kk = 0; kk < 4; kk++) {
            qh[kk][0] = rh0[kk * 8 + c];     qh[kk][1] = rh8[kk * 8 + c];
            qh[kk][2] = rh0[kk * 8 + c + 4]; qh[kk][3] = rh8[kk * 8 + c + 4];
            ql[kk][0] = rl0[kk * 8 + c];     ql[kk][1] = rl8[kk * 8 + c];
            ql[kk][2] = rl0[kk * 8 + c + 4]; ql[kk][3] = rl8[kk * 8 + c + 4];
        }
    }

    float o[8][4] = {};
    float lsum_lo = 0.0f, lsum_hi = 0.0f;

    aload(0, 0); CP_COMMIT();
    aload(1, 1); CP_COMMIT();

    for (int kt = 0; kt < SEQ / 64; kt++) {
        const int k0 = kt * 64;

        CP_WAIT1();
        __syncthreads();
        if (kt + 2 < SEQ / 64) aload(kt + 2, (kt + 2) % 3);
        CP_COMMIT();

        unsigned* st  = sm + (kt % 3) * 6912;
        unsigned* sK  = st;
        unsigned* sVh = st + 2304;
        unsigned* sVl = st + 4608;

        // S = Q K^T (2-term fp16)
        float s[8][4] = {};
        #pragma unroll
        for (int kk = 0; kk < 4; kk++) {
            #pragma unroll
            for (int nt = 0; nt < 8; nt++) {
                int n = nt * 8 + r;
                unsigned b0 = sK[n * 36 + kk * 8 + c];
                unsigned b1 = sK[n * 36 + kk * 8 + c + 4];
                mma_h(s[nt], qh[kk], b0, b1);
                mma_h(s[nt], ql[kk], b0, b1);
            }
        }

        // fixed-max softmax: p = exp(s/8 + mask); accumulate l (in registers)
        #pragma unroll
        for (int nt = 0; nt < 8; nt++) {
            int col = k0 + nt * 8 + 2 * c;
            float mk0 = __ldg(mask + (size_t)bb * SEQ + col);
            float mk1 = __ldg(mask + (size_t)bb * SEQ + col + 1);
            s[nt][0] = __expf(fmaf(s[nt][0], 0.125f, mk0));
            s[nt][1] = __expf(fmaf(s[nt][1], 0.125f, mk1));
            s[nt][2] = __expf(fmaf(s[nt][2], 0.125f, mk0));
            s[nt][3] = __expf(fmaf(s[nt][3], 0.125f, mk1));
            lsum_lo += s[nt][0] + s[nt][1];
            lsum_hi += s[nt][2] + s[nt][3];
        }

        // P: C-fragment layout == A-fragment layout. Split in registers.
        unsigned aPh[4][4], aPl[4][4];
        #pragma unroll
        for (int kk = 0; kk < 4; kk++) {
            split2h(s[2*kk][0],   s[2*kk][1],   aPh[kk][0], aPl[kk][0]);
            split2h(s[2*kk][2],   s[2*kk][3],   aPh[kk][1], aPl[kk][1]);
            split2h(s[2*kk+1][0], s[2*kk+1][1], aPh[kk][2], aPl[kk][2]);
            split2h(s[2*kk+1][2], s[2*kk+1][3], aPh[kk][3], aPl[kk][3]);
        }

        // O += P V (3-term fp16), B from smem V^T
        #pragma unroll
        for (int kk = 0; kk < 4; kk++) {
            #pragma unroll
            for (int nt = 0; nt < 8; nt++) {
                int d = nt * 8 + r;
                unsigned bh0 = sVh[d * 36 + kk * 8 + c];
                unsigned bh1 = sVh[d * 36 + kk * 8 + c + 4];
                unsigned bl0 = sVl[d * 36 + kk * 8 + c];
                unsigned bl1 = sVl[d * 36 + kk * 8 + c + 4];
                mma_h(o[nt], aPh[kk], bh0, bh1);
                mma_h(o[nt], aPl[kk], bh0, bh1);
                mma_h(o[nt], aPh[kk], bl0, bl1);
            }
        }
    }

    // reduce l across the quad (c=0..3 share the q-row)
    #pragma unroll
    for (int d = 1; d <= 2; d <<= 1) {
        lsum_lo += __shfl_xor_sync(0xffffffffu, lsum_lo, d);
        lsum_hi += __shfl_xor_sync(0xffffffffu, lsum_hi, d);
    }
    float inv_lo = 1.0f / lsum_lo;
    float inv_hi = 1.0f / lsum_hi;

    // write ctx directly as split fp16 [m][n]
    uint32_t* Ch = (uint32_t*)g_cxh;
    uint32_t* Cl = (uint32_t*)g_cxl;
    size_t mrow  = (size_t)bb * SEQ + q0 + warp * 16 + r;
    size_t mrow8 = mrow + 8;
    #pragma unroll
    for (int nt = 0; nt < 8; nt++) {
        int col = h * 64 + nt * 8 + 2 * c;
        split2h(o[nt][0] * inv_lo, o[nt][1] * inv_lo,
                Ch[(mrow  * HID + col) / 2], Cl[(mrow  * HID + col) / 2]);
        split2h(o[nt][2] * inv_hi, o[nt][3] * inv_hi,
                Ch[(mrow8 * HID + col) / 2], Cl[(mrow8 * HID + col) / 2]);
    }
}

// ---------------------------------------------------------------------------

extern "C" void kernel_launch(void* const* d_in, const int* in_sizes, int n_in,
                              void* d_out, int out_size)
{
    const float* hs   = (const float*)d_in[0];
    const float* mask = (const float*)d_in[1];
    const float* Wq   = (const float*)d_in[2];
    const float* bq   = (const float*)d_in[3];
    const float* Wk   = (const float*)d_in[4];
    const float* bk   = (const float*)d_in[5];
    const float* Wv   = (const float*)d_in[6];
    const float* bv   = (const float*)d_in[7];
    const float* Wo   = (const float*)d_in[8];
    const float* bo   = (const float*)d_in[9];
    float* out = (float*)d_out;

    __half *hsh, *hsl, *wh, *wl, *cxh, *cxl;
    cudaGetSymbolAddress((void**)&hsh, g_hsh);
    cudaGetSymbolAddress((void**)&hsl, g_hsl);
    cudaGetSymbolAddress((void**)&wh,  g_wh);
    cudaGetSymbolAddress((void**)&wl,  g_wl);
    cudaGetSymbolAddress((void**)&cxh, g_cxh);
    cudaGetSymbolAddress((void**)&cxl, g_cxl);

    const int gemm_smem = 3 * 7680 * 4;   // 92,160 B
    const int attn_smem = 3 * 6912 * 4;   // 82,944 B
    cudaFuncSetAttribute(gemm16, cudaFuncAttributeMaxDynamicSharedMemorySize, gemm_smem);
    cudaFuncSetAttribute(attn16, cudaFuncAttributeMaxDynamicSharedMemorySize, attn_smem);

    dim3 blk(256);
    const int nHS = MROWS * HID / 4;   // 1,048,576 float4
    const int nW  = HID * HID / 4;     // 262,144 float4

    // presplit inputs
    split16<<<nHS / 256, blk>>>((const float4*)hs, (uint2*)hsh, (uint2*)hsl, nHS);
    split16<<<nW / 256, blk>>>((const float4*)Wq, (uint2*)(wh + 0 * HID * HID), (uint2*)(wl + 0 * HID * HID), nW);
    split16<<<nW / 256, blk>>>((const float4*)Wk, (uint2*)(wh + 1 * HID * HID), (uint2*)(wl + 1 * HID * HID), nW);
    split16<<<nW / 256, blk>>>((const float4*)Wv, (uint2*)(wh + 2 * HID * HID), (uint2*)(wl + 2 * HID * HID), nW);
    split16<<<nW / 256, blk>>>((const float4*)Wo, (uint2*)(wh + 3 * HID * HID), (uint2*)(wl + 3 * HID * HID), nW);

    dim3 gG(HID / 64, MROWS / 128);    // (16, 32)
    gemm16<<<gG, blk, gemm_smem>>>(hsh, hsl, wh + 0 * HID * HID, wl + 0 * HID * HID, bq, nullptr, 1);
    gemm16<<<gG, blk, gemm_smem>>>(hsh, hsl, wh + 1 * HID * HID, wl + 1 * HID * HID, bk, nullptr, 2);
    gemm16<<<gG, blk, gemm_smem>>>(hsh, hsl, wh + 2 * HID * HID, wl + 2 * HID * HID, bv, nullptr, 3);

    dim3 gT(SEQ / 64, BH);             // (32, 32)
    transV<<<gT, blk>>>();

    dim3 gA(SEQ / 128, BH);            // (16, 32)
    attn16<<<gA, blk, attn_smem>>>(mask);

    gemm16<<<gG, blk, gemm_smem>>>(cxh, cxl, wh + 3 * HID * HID, wl + 3 * HID * HID, bo, out, 0);
}

// round 9
// speedup vs baseline: 1.8709x; 1.3736x over previous
#include <cuda_runtime.h>
#include <cuda_fp16.h>
#include <cstdint>

#define BATCH 2
#define SEQ   2048
#define HID   1024
#define NHEAD 16
#define HDIM  64
#define MROWS (BATCH*SEQ)   // 4096
#define BH    (BATCH*NHEAD) // 32

// ---------------- device scratch (allocation-free rule) ----------------
__device__ __half g_hsh[MROWS*HID], g_hsl[MROWS*HID];   // hidden states hi/lo
__device__ __half g_wf[4*HID*HID];                      // Wq,Wk,Wv,Wo plain fp16
__device__ __half g_qf[BH*SEQ*HDIM];                    // Q plain [bh][s][d]
__device__ __half g_kf[BH*SEQ*HDIM];                    // K plain [bh][s][d]
__device__ __half g_vf[BH*SEQ*HDIM];                    // V plain [bh][s][d]
__device__ __half g_vtf[BH*HDIM*SEQ];                   // V^T plain [bh][d][s]
__device__ __half g_cxh[MROWS*HID], g_cxl[MROWS*HID];   // ctx split [m][n]

// ---------------- helpers ----------------
__device__ __forceinline__ unsigned pack2h(__half a, __half b) {
    __half2 t(a, b);
    return *reinterpret_cast<unsigned*>(&t);
}
__device__ __forceinline__ void split2h(float x0, float x1, unsigned &hi, unsigned &lo) {
    __half h0 = __float2half_rn(x0);
    __half h1 = __float2half_rn(x1);
    __half l0 = __float2half_rn(x0 - __half2float(h0));
    __half l1 = __float2half_rn(x1 - __half2float(h1));
    hi = pack2h(h0, h1); lo = pack2h(l0, l1);
}
__device__ __forceinline__ void mma_h(float* c, const unsigned* a,
                                      unsigned b0, unsigned b1) {
    asm volatile(
        "mma.sync.aligned.m16n8k16.row.col.f32.f16.f16.f32 "
        "{%0,%1,%2,%3},{%4,%5,%6,%7},{%8,%9},{%0,%1,%2,%3};\n"
        : "+f"(c[0]), "+f"(c[1]), "+f"(c[2]), "+f"(c[3])
        : "r"(a[0]), "r"(a[1]), "r"(a[2]), "r"(a[3]), "r"(b0), "r"(b1));
}
__device__ __forceinline__ uint32_t s2u(const void* p) {
    uint32_t a;
    asm("{ .reg .u64 t; cvta.to.shared.u64 t, %1; cvt.u32.u64 %0, t; }" : "=r"(a) : "l"(p));
    return a;
}
__device__ __forceinline__ void cp16(uint32_t saddr, const void* gaddr) {
    asm volatile("cp.async.cg.shared.global [%0], [%1], 16;" :: "r"(saddr), "l"(gaddr));
}
#define CP_COMMIT() asm volatile("cp.async.commit_group;" ::: "memory")
#define CP_WAIT1()  asm volatile("cp.async.wait_group 1;" ::: "memory")

// ---------------- fp32 -> fp16 hi/lo split ----------------
__global__ void split16(const float4* __restrict__ in,
                        uint2* __restrict__ hi, uint2* __restrict__ lo, int n4)
{
    int i = blockIdx.x * 256 + threadIdx.x;
    if (i >= n4) return;
    float4 v = in[i];
    uint2 h, l;
    split2h(v.x, v.y, h.x, l.x);
    split2h(v.z, v.w, h.y, l.y);
    hi[i] = h; lo[i] = l;
}

// ---------------- fp32 -> fp16 plain convert ----------------
__global__ void conv16(const float4* __restrict__ in, uint2* __restrict__ outp, int n4)
{
    int i = blockIdx.x * 256 + threadIdx.x;
    if (i >= n4) return;
    float4 v = in[i];
    uint2 o;
    o.x = pack2h(__float2half_rn(v.x), __float2half_rn(v.y));
    o.y = pack2h(__float2half_rn(v.z), __float2half_rn(v.w));
    outp[i] = o;
}

// ---------------- GEMM: C = A @ W^T + bias (2-term: (Ah+Al) x Wf) ----------------
// tile 128x64, kstep 32 halves. Stage 6400 u32: AH @ 0 (128x20), AL @ 2560, WF @ 5120 (64x20).
// outH != nullptr: head-split plain fp16; else fp32 row-major to outF.
__global__ __launch_bounds__(256, 2) void gemm16(
    const __half* __restrict__ Ahi, const __half* __restrict__ Alo,
    const __half* __restrict__ Wf,
    const float* __restrict__ bias, float* __restrict__ outF, __half* __restrict__ outH)
{
    extern __shared__ unsigned sm[];

    const int tid  = threadIdx.x;
    const int lane = tid & 31, warp = tid >> 5;
    const int wm = warp >> 1, wn = warp & 1;
    const int r = lane >> 2, c = lane & 3;
    const int m0 = blockIdx.y * 128, n0 = blockIdx.x * 64;

    const uint32_t* A32h = (const uint32_t*)Ahi;
    const uint32_t* A32l = (const uint32_t*)Alo;
    const uint32_t* W32  = (const uint32_t*)Wf;

    const uint32_t smbase = s2u(sm);

    auto gload = [&](int kc, int st) {
        uint32_t base = smbase + (uint32_t)st * 6400u * 4u;
        #pragma unroll
        for (int j = 0; j < 2; j++) {
            int idx = tid + j * 256;             // 0..511
            int row = idx >> 2, v = idx & 3;
            size_t go = (size_t)(m0 + row) * 512 + kc * 16 + v * 4;
            uint32_t so = (uint32_t)(row * 20 + v * 4) * 4u;
            cp16(base + so,            A32h + go);
            cp16(base + 2560u*4u + so, A32l + go);
        }
        {
            int row = tid >> 2, v = tid & 3;
            size_t go = (size_t)(n0 + row) * 512 + kc * 16 + v * 4;
            uint32_t so = (uint32_t)(row * 20 + v * 4) * 4u;
            cp16(base + 5120u*4u + so, W32 + go);
        }
    };

    float acc[2][4][4] = {};

    gload(0, 0); CP_COMMIT();
    gload(1, 1); CP_COMMIT();

    for (int kc = 0; kc < 32; kc++) {
        CP_WAIT1();
        __syncthreads();
        if (kc + 2 < 32) gload(kc + 2, (kc + 2) % 3);
        CP_COMMIT();

        unsigned* st   = sm + (kc % 3) * 6400;
        unsigned* sAhi = st;
        unsigned* sAlo = st + 2560;
        unsigned* sWf  = st + 5120;

        #pragma unroll
        for (int kk = 0; kk < 2; kk++) {
            unsigned ah[2][4], al[2][4];
            #pragma unroll
            for (int mt = 0; mt < 2; mt++) {
                int base = wm * 32 + mt * 16;
                ah[mt][0] = sAhi[(base + r)     * 20 + kk * 8 + c];
                ah[mt][1] = sAhi[(base + r + 8) * 20 + kk * 8 + c];
                ah[mt][2] = sAhi[(base + r)     * 20 + kk * 8 + c + 4];
                ah[mt][3] = sAhi[(base + r + 8) * 20 + kk * 8 + c + 4];
                al[mt][0] = sAlo[(base + r)     * 20 + kk * 8 + c];
                al[mt][1] = sAlo[(base + r + 8) * 20 + kk * 8 + c];
                al[mt][2] = sAlo[(base + r)     * 20 + kk * 8 + c + 4];
                al[mt][3] = sAlo[(base + r + 8) * 20 + kk * 8 + c + 4];
            }
            #pragma unroll
            for (int nt = 0; nt < 4; nt++) {
                int n = wn * 32 + nt * 8 + r;
                unsigned b0 = sWf[n * 20 + kk * 8 + c];
                unsigned b1 = sWf[n * 20 + kk * 8 + c + 4];
                #pragma unroll
                for (int mt = 0; mt < 2; mt++) {
                    mma_h(acc[mt][nt], ah[mt], b0, b1);
                    mma_h(acc[mt][nt], al[mt], b0, b1);
                }
            }
        }
    }

    uint32_t* OH32 = (uint32_t*)outH;

    #pragma unroll
    for (int mt = 0; mt < 2; mt++) {
        #pragma unroll
        for (int nt = 0; nt < 4; nt++) {
            int row = m0 + wm * 32 + mt * 16 + r;
            int col = n0 + wn * 32 + nt * 8 + 2 * c;
            float b0v = bias[col], b1v = bias[col + 1];
            float v00 = acc[mt][nt][0] + b0v;
            float v01 = acc[mt][nt][1] + b1v;
            float v10 = acc[mt][nt][2] + b0v;
            float v11 = acc[mt][nt][3] + b1v;
            if (outH == nullptr) {
                outF[(size_t)row * HID + col]           = v00;
                outF[(size_t)row * HID + col + 1]       = v01;
                outF[(size_t)(row + 8) * HID + col]     = v10;
                outF[(size_t)(row + 8) * HID + col + 1] = v11;
            } else {
                int hh = col >> 6, d = col & 63;
                int bb0 = row >> 11, s0 = row & (SEQ - 1);
                int bb1 = (row + 8) >> 11, s1 = (row + 8) & (SEQ - 1);
                size_t o0 = ((((size_t)(bb0 * NHEAD + hh)) * SEQ + s0) * HDIM + d) / 2;
                size_t o1 = ((((size_t)(bb1 * NHEAD + hh)) * SEQ + s1) * HDIM + d) / 2;
                OH32[o0] = pack2h(__float2half_rn(v00), __float2half_rn(v01));
                OH32[o1] = pack2h(__float2half_rn(v10), __float2half_rn(v11));
            }
        }
    }
}

// ---------------- V transpose: [bh][s][d] -> [bh][d][s] (plain) ----------------
__global__ __launch_bounds__(256) void transV()
{
    __shared__ __half t[64][66];
    const int tid = threadIdx.x;
    const int s0  = blockIdx.x * 64;
    const int bh  = blockIdx.y;

    const uint32_t* V32 = (const uint32_t*)g_vf + (size_t)bh * SEQ * 32;
    uint32_t* T32 = (uint32_t*)g_vtf + (size_t)bh * HDIM * (SEQ / 2);

    #pragma unroll
    for (int j = 0; j < 8; j++) {
        int idx = tid + j * 256;
        int row = idx >> 5, p = idx & 31;
        *(uint32_t*)&t[row][2 * p] = V32[(size_t)(s0 + row) * 32 + p];
    }
    __syncthreads();
    #pragma unroll
    for (int j = 0; j < 8; j++) {
        int idx = tid + j * 256;
        int d = idx >> 5, q = idx & 31;
        T32[(size_t)d * (SEQ / 2) + s0 / 2 + q] = pack2h(t[2 * q][d], t[2 * q + 1][d]);
    }
}

// ---------------- fused attention ----------------
// CTA: 128 q-rows of one (b,h), 8 warps x 16 q, 32 k-tiles of 64.
// S = Qf x Kf (1-term). P split in regs. PV = (Ph+Pl) x Vf (2-term).
// Stage 4608 u32: K @ 0 (64x36), Vf @ 2304. cp.async 3-stage.
__global__ __launch_bounds__(256, 2) void attn16(const float* __restrict__ mask)
{
    extern __shared__ unsigned sm[];

    const int tid  = threadIdx.x;
    const int lane = tid & 31, warp = tid >> 5;
    const int r = lane >> 2, c = lane & 3;
    const int bh = blockIdx.y;
    const int bb = bh >> 4, h = bh & 15;
    const int q0 = blockIdx.x * 128;

    const uint32_t* Qf32 = (const uint32_t*)g_qf + (size_t)bh * SEQ * 32;
    const uint32_t* Kf32 = (const uint32_t*)g_kf + (size_t)bh * SEQ * 32;
    const uint32_t* T32  = (const uint32_t*)g_vtf + (size_t)bh * HDIM * (SEQ / 2);

    const uint32_t smbase = s2u(sm);

    auto aload = [&](int kt, int st) {
        uint32_t base = smbase + (uint32_t)st * 4608u * 4u;
        const int k0 = kt * 64;
        #pragma unroll
        for (int j = 0; j < 2; j++) {
            int idx = tid + j * 256;             // 0..511
            int row = idx >> 3, v = idx & 7;
            uint32_t so = (uint32_t)(row * 36 + v * 4) * 4u;
            cp16(base + so,            Kf32 + (size_t)(k0 + row) * 32 + v * 4);
            cp16(base + 2304u*4u + so, T32 + (size_t)row * (SEQ / 2) + k0 / 2 + v * 4);
        }
    };

    // Q fragments (plain fp16), 16 q-rows per warp, in registers
    unsigned qf[4][4];
    {
        int qr = q0 + warp * 16 + r;
        const uint32_t* rf0 = Qf32 + (size_t)qr * 32;
        const uint32_t* rf8 = Qf32 + (size_t)(qr + 8) * 32;
        #pragma unroll
        for (int kk = 0; kk < 4; kk++) {
            qf[kk][0] = rf0[kk * 8 + c];     qf[kk][1] = rf8[kk * 8 + c];
            qf[kk][2] = rf0[kk * 8 + c + 4]; qf[kk][3] = rf8[kk * 8 + c + 4];
        }
    }

    float o[8][4] = {};
    float lsum_lo = 0.0f, lsum_hi = 0.0f;

    aload(0, 0); CP_COMMIT();
    aload(1, 1); CP_COMMIT();

    for (int kt = 0; kt < SEQ / 64; kt++) {
        const int k0 = kt * 64;

        CP_WAIT1();
        __syncthreads();
        if (kt + 2 < SEQ / 64) aload(kt + 2, (kt + 2) % 3);
        CP_COMMIT();

        unsigned* st = sm + (kt % 3) * 4608;
        unsigned* sK = st;
        unsigned* sV = st + 2304;

        // S = Q K^T (1-term fp16)
        float s[8][4] = {};
        #pragma unroll
        for (int kk = 0; kk < 4; kk++) {
            #pragma unroll
            for (int nt = 0; nt < 8; nt++) {
                int n = nt * 8 + r;
                unsigned b0 = sK[n * 36 + kk * 8 + c];
                unsigned b1 = sK[n * 36 + kk * 8 + c + 4];
                mma_h(s[nt], qf[kk], b0, b1);
            }
        }

        // fixed-max softmax: p = exp(s/8 + mask); accumulate l in registers
        #pragma unroll
        for (int nt = 0; nt < 8; nt++) {
            int col = k0 + nt * 8 + 2 * c;
            float mk0 = __ldg(mask + (size_t)bb * SEQ + col);
            float mk1 = __ldg(mask + (size_t)bb * SEQ + col + 1);
            s[nt][0] = __expf(fmaf(s[nt][0], 0.125f, mk0));
            s[nt][1] = __expf(fmaf(s[nt][1], 0.125f, mk1));
            s[nt][2] = __expf(fmaf(s[nt][2], 0.125f, mk0));
            s[nt][3] = __expf(fmaf(s[nt][3], 0.125f, mk1));
            lsum_lo += s[nt][0] + s[nt][1];
            lsum_hi += s[nt][2] + s[nt][3];
        }

        // P: C-frag layout == A-frag layout; split hi/lo in registers
        unsigned aPh[4][4], aPl[4][4];
        #pragma unroll
        for (int kk = 0; kk < 4; kk++) {
            split2h(s[2*kk][0],   s[2*kk][1],   aPh[kk][0], aPl[kk][0]);
            split2h(s[2*kk][2],   s[2*kk][3],   aPh[kk][1], aPl[kk][1]);
            split2h(s[2*kk+1][0], s[2*kk+1][1], aPh[kk][2], aPl[kk][2]);
            split2h(s[2*kk+1][2], s[2*kk+1][3], aPh[kk][3], aPl[kk][3]);
        }

        // O += P V (2-term), B from smem V^T (plain)
        #pragma unroll
        for (int kk = 0; kk < 4; kk++) {
            #pragma unroll
            for (int nt = 0; nt < 8; nt++) {
                int d = nt * 8 + r;
                unsigned b0 = sV[d * 36 + kk * 8 + c];
                unsigned b1 = sV[d * 36 + kk * 8 + c + 4];
                mma_h(o[nt], aPh[kk], b0, b1);
                mma_h(o[nt], aPl[kk], b0, b1);
            }
        }
    }

    // reduce l across the quad (c=0..3 share the q-row)
    #pragma unroll
    for (int d = 1; d <= 2; d <<= 1) {
        lsum_lo += __shfl_xor_sync(0xffffffffu, lsum_lo, d);
        lsum_hi += __shfl_xor_sync(0xffffffffu, lsum_hi, d);
    }
    float inv_lo = 1.0f / lsum_lo;
    float inv_hi = 1.0f / lsum_hi;

    // write ctx as split fp16 [m][n]
    uint32_t* Ch = (uint32_t*)g_cxh;
    uint32_t* Cl = (uint32_t*)g_cxl;
    size_t mrow  = (size_t)bb * SEQ + q0 + warp * 16 + r;
    size_t mrow8 = mrow + 8;
    #pragma unroll
    for (int nt = 0; nt < 8; nt++) {
        int col = h * 64 + nt * 8 + 2 * c;
        split2h(o[nt][0] * inv_lo, o[nt][1] * inv_lo,
                Ch[(mrow  * HID + col) / 2], Cl[(mrow  * HID + col) / 2]);
        split2h(o[nt][2] * inv_hi, o[nt][3] * inv_hi,
                Ch[(mrow8 * HID + col) / 2], Cl[(mrow8 * HID + col) / 2]);
    }
}

// ---------------------------------------------------------------------------

extern "C" void kernel_launch(void* const* d_in, const int* in_sizes, int n_in,
                              void* d_out, int out_size)
{
    const float* hs   = (const float*)d_in[0];
    const float* mask = (const float*)d_in[1];
    const float* Wq   = (const float*)d_in[2];
    const float* bq   = (const float*)d_in[3];
    const float* Wk   = (const float*)d_in[4];
    const float* bk   = (const float*)d_in[5];
    const float* Wv   = (const float*)d_in[6];
    const float* bv   = (const float*)d_in[7];
    const float* Wo   = (const float*)d_in[8];
    const float* bo   = (const float*)d_in[9];
    float* out = (float*)d_out;

    __half *hsh, *hsl, *wf, *qf, *kf, *vf, *cxh, *cxl;
    cudaGetSymbolAddress((void**)&hsh, g_hsh);
    cudaGetSymbolAddress((void**)&hsl, g_hsl);
    cudaGetSymbolAddress((void**)&wf,  g_wf);
    cudaGetSymbolAddress((void**)&qf,  g_qf);
    cudaGetSymbolAddress((void**)&kf,  g_kf);
    cudaGetSymbolAddress((void**)&vf,  g_vf);
    cudaGetSymbolAddress((void**)&cxh, g_cxh);
    cudaGetSymbolAddress((void**)&cxl, g_cxl);

    const int gemm_smem = 3 * 6400 * 4;   // 76,800 B
    const int attn_smem = 3 * 4608 * 4;   // 55,296 B
    cudaFuncSetAttribute(gemm16, cudaFuncAttributeMaxDynamicSharedMemorySize, gemm_smem);
    cudaFuncSetAttribute(attn16, cudaFuncAttributeMaxDynamicSharedMemorySize, attn_smem);

    dim3 blk(256);
    const int nHS = MROWS * HID / 4;   // 1,048,576 float4
    const int nW  = HID * HID / 4;     // 262,144 float4

    // prepare operands
    split16<<<nHS / 256, blk>>>((const float4*)hs, (uint2*)hsh, (uint2*)hsl, nHS);
    conv16<<<nW / 256, blk>>>((const float4*)Wq, (uint2*)(wf + 0 * HID * HID), nW);
    conv16<<<nW / 256, blk>>>((const float4*)Wk, (uint2*)(wf + 1 * HID * HID), nW);
    conv16<<<nW / 256, blk>>>((const float4*)Wv, (uint2*)(wf + 2 * HID * HID), nW);
    conv16<<<nW / 256, blk>>>((const float4*)Wo, (uint2*)(wf + 3 * HID * HID), nW);

    dim3 gG(HID / 64, MROWS / 128);    // (16, 32)
    gemm16<<<gG, blk, gemm_smem>>>(hsh, hsl, wf + 0 * HID * HID, bq, nullptr, qf);
    gemm16<<<gG, blk, gemm_smem>>>(hsh, hsl, wf + 1 * HID * HID, bk, nullptr, kf);
    gemm16<<<gG, blk, gemm_smem>>>(hsh, hsl, wf + 2 * HID * HID, bv, nullptr, vf);

    dim3 gT(SEQ / 64, BH);             // (32, 32)
    transV<<<gT, blk>>>();

    dim3 gA(SEQ / 128, BH);            // (16, 32)
    attn16<<<gA, blk, attn_smem>>>(mask);

    gemm16<<<gG, blk, gemm_smem>>>(cxh, cxl, wf + 3 * HID * HID, bo, out, nullptr);
}

// round 10
// speedup vs baseline: 2.4219x; 1.2945x over previous
#include <cuda_runtime.h>
#include <cuda_fp16.h>
#include <cstdint>

#define BATCH 2
#define SEQ   2048
#define HID   1024
#define NHEAD 16
#define HDIM  64
#define MROWS (BATCH*SEQ)   // 4096
#define BH    (BATCH*NHEAD) // 32

// ---------------- device scratch (allocation-free rule) ----------------
__device__ __half g_hsf[MROWS*HID];                     // hidden states plain fp16
__device__ __half g_wf[4*HID*HID];                      // Wq,Wk,Wv,Wo plain fp16
__device__ __half g_qf[BH*SEQ*HDIM];                    // Q plain [bh][s][d]
__device__ __half g_kf[BH*SEQ*HDIM];                    // K plain [bh][s][d]
__device__ __half g_vf[BH*SEQ*HDIM];                    // V plain [bh][s][d]
__device__ __half g_vtf[BH*HDIM*SEQ];                   // V^T plain [bh][d][s]
__device__ __half g_cxf[MROWS*HID];                     // ctx plain [m][n]

// ---------------- helpers ----------------
__device__ __forceinline__ unsigned pack2h(__half a, __half b) {
    __half2 t(a, b);
    return *reinterpret_cast<unsigned*>(&t);
}
__device__ __forceinline__ void split2h(float x0, float x1, unsigned &hi, unsigned &lo) {
    __half h0 = __float2half_rn(x0);
    __half h1 = __float2half_rn(x1);
    __half l0 = __float2half_rn(x0 - __half2float(h0));
    __half l1 = __float2half_rn(x1 - __half2float(h1));
    hi = pack2h(h0, h1); lo = pack2h(l0, l1);
}
__device__ __forceinline__ void mma_h(float* c, const unsigned* a,
                                      unsigned b0, unsigned b1) {
    asm volatile(
        "mma.sync.aligned.m16n8k16.row.col.f32.f16.f16.f32 "
        "{%0,%1,%2,%3},{%4,%5,%6,%7},{%8,%9},{%0,%1,%2,%3};\n"
        : "+f"(c[0]), "+f"(c[1]), "+f"(c[2]), "+f"(c[3])
        : "r"(a[0]), "r"(a[1]), "r"(a[2]), "r"(a[3]), "r"(b0), "r"(b1));
}
__device__ __forceinline__ uint32_t s2u(const void* p) {
    uint32_t a;
    asm("{ .reg .u64 t; cvta.to.shared.u64 t, %1; cvt.u32.u64 %0, t; }" : "=r"(a) : "l"(p));
    return a;
}
__device__ __forceinline__ void cp16(uint32_t saddr, const void* gaddr) {
    asm volatile("cp.async.cg.shared.global [%0], [%1], 16;" :: "r"(saddr), "l"(gaddr));
}
#define CP_COMMIT() asm volatile("cp.async.commit_group;" ::: "memory")
#define CP_WAIT1()  asm volatile("cp.async.wait_group 1;" ::: "memory")

// ---------------- fp32 -> fp16 plain convert ----------------
__global__ void conv16(const float4* __restrict__ in, uint2* __restrict__ outp, int n4)
{
    int i = blockIdx.x * 256 + threadIdx.x;
    if (i >= n4) return;
    float4 v = in[i];
    uint2 o;
    o.x = pack2h(__float2half_rn(v.x), __float2half_rn(v.y));
    o.y = pack2h(__float2half_rn(v.z), __float2half_rn(v.w));
    outp[i] = o;
}

// ---------------- GEMM: C = A @ W^T + bias (1-term plain fp16) ----------------
// tile 128x64, kstep 32 halves. Stage 3840 u32: A @ 0 (128x20), W @ 2560 (64x20).
// outH != nullptr: head-split plain fp16; else fp32 row-major to outF.
__global__ __launch_bounds__(256, 2) void gemm16(
    const __half* __restrict__ Af, const __half* __restrict__ Wf,
    const float* __restrict__ bias, float* __restrict__ outF, __half* __restrict__ outH)
{
    extern __shared__ unsigned sm[];

    const int tid  = threadIdx.x;
    const int lane = tid & 31, warp = tid >> 5;
    const int wm = warp >> 1, wn = warp & 1;
    const int r = lane >> 2, c = lane & 3;
    const int m0 = blockIdx.y * 128, n0 = blockIdx.x * 64;

    const uint32_t* A32 = (const uint32_t*)Af;
    const uint32_t* W32 = (const uint32_t*)Wf;

    const uint32_t smbase = s2u(sm);

    auto gload = [&](int kc, int st) {
        uint32_t base = smbase + (uint32_t)st * 3840u * 4u;
        #pragma unroll
        for (int j = 0; j < 2; j++) {
            int idx = tid + j * 256;             // 0..511
            int row = idx >> 2, v = idx & 3;
            size_t go = (size_t)(m0 + row) * 512 + kc * 16 + v * 4;
            cp16(base + (uint32_t)(row * 20 + v * 4) * 4u, A32 + go);
        }
        {
            int row = tid >> 2, v = tid & 3;
            size_t go = (size_t)(n0 + row) * 512 + kc * 16 + v * 4;
            cp16(base + 2560u*4u + (uint32_t)(row * 20 + v * 4) * 4u, W32 + go);
        }
    };

    float acc[2][4][4] = {};

    gload(0, 0); CP_COMMIT();
    gload(1, 1); CP_COMMIT();

    for (int kc = 0; kc < 32; kc++) {
        CP_WAIT1();
        __syncthreads();
        if (kc + 2 < 32) gload(kc + 2, (kc + 2) % 3);
        CP_COMMIT();

        unsigned* st = sm + (kc % 3) * 3840;
        unsigned* sA = st;
        unsigned* sW = st + 2560;

        #pragma unroll
        for (int kk = 0; kk < 2; kk++) {
            unsigned a[2][4];
            #pragma unroll
            for (int mt = 0; mt < 2; mt++) {
                int base = wm * 32 + mt * 16;
                a[mt][0] = sA[(base + r)     * 20 + kk * 8 + c];
                a[mt][1] = sA[(base + r + 8) * 20 + kk * 8 + c];
                a[mt][2] = sA[(base + r)     * 20 + kk * 8 + c + 4];
                a[mt][3] = sA[(base + r + 8) * 20 + kk * 8 + c + 4];
            }
            #pragma unroll
            for (int nt = 0; nt < 4; nt++) {
                int n = wn * 32 + nt * 8 + r;
                unsigned b0 = sW[n * 20 + kk * 8 + c];
                unsigned b1 = sW[n * 20 + kk * 8 + c + 4];
                #pragma unroll
                for (int mt = 0; mt < 2; mt++)
                    mma_h(acc[mt][nt], a[mt], b0, b1);
            }
        }
    }

    uint32_t* OH32 = (uint32_t*)outH;

    #pragma unroll
    for (int mt = 0; mt < 2; mt++) {
        #pragma unroll
        for (int nt = 0; nt < 4; nt++) {
            int row = m0 + wm * 32 + mt * 16 + r;
            int col = n0 + wn * 32 + nt * 8 + 2 * c;
            float b0v = bias[col], b1v = bias[col + 1];
            float v00 = acc[mt][nt][0] + b0v;
            float v01 = acc[mt][nt][1] + b1v;
            float v10 = acc[mt][nt][2] + b0v;
            float v11 = acc[mt][nt][3] + b1v;
            if (outH == nullptr) {
                outF[(size_t)row * HID + col]           = v00;
                outF[(size_t)row * HID + col + 1]       = v01;
                outF[(size_t)(row + 8) * HID + col]     = v10;
                outF[(size_t)(row + 8) * HID + col + 1] = v11;
            } else {
                int hh = col >> 6, d = col & 63;
                int bb0 = row >> 11, s0 = row & (SEQ - 1);
                int bb1 = (row + 8) >> 11, s1 = (row + 8) & (SEQ - 1);
                size_t o0 = ((((size_t)(bb0 * NHEAD + hh)) * SEQ + s0) * HDIM + d) / 2;
                size_t o1 = ((((size_t)(bb1 * NHEAD + hh)) * SEQ + s1) * HDIM + d) / 2;
                OH32[o0] = pack2h(__float2half_rn(v00), __float2half_rn(v01));
                OH32[o1] = pack2h(__float2half_rn(v10), __float2half_rn(v11));
            }
        }
    }
}

// ---------------- V transpose: [bh][s][d] -> [bh][d][s] (plain) ----------------
__global__ __launch_bounds__(256) void transV()
{
    __shared__ __half t[64][66];
    const int tid = threadIdx.x;
    const int s0  = blockIdx.x * 64;
    const int bh  = blockIdx.y;

    const uint32_t* V32 = (const uint32_t*)g_vf + (size_t)bh * SEQ * 32;
    uint32_t* T32 = (uint32_t*)g_vtf + (size_t)bh * HDIM * (SEQ / 2);

    #pragma unroll
    for (int j = 0; j < 8; j++) {
        int idx = tid + j * 256;
        int row = idx >> 5, p = idx & 31;
        *(uint32_t*)&t[row][2 * p] = V32[(size_t)(s0 + row) * 32 + p];
    }
    __syncthreads();
    #pragma unroll
    for (int j = 0; j < 8; j++) {
        int idx = tid + j * 256;
        int d = idx >> 5, q = idx & 31;
        T32[(size_t)d * (SEQ / 2) + s0 / 2 + q] = pack2h(t[2 * q][d], t[2 * q + 1][d]);
    }
}

// ---------------- fused attention ----------------
// CTA: 128 q-rows of one (b,h), 8 warps x 16 q, 32 k-tiles of 64.
// S = Qf x Kf (1-term). P split in regs. PV = (Ph+Pl) x Vf (2-term).
// Stage 4608 u32: K @ 0 (64x36), Vf @ 2304. cp.async 3-stage.
__global__ __launch_bounds__(256, 2) void attn16(const float* __restrict__ mask)
{
    extern __shared__ unsigned sm[];

    const int tid  = threadIdx.x;
    const int lane = tid & 31, warp = tid >> 5;
    const int r = lane >> 2, c = lane & 3;
    const int bh = blockIdx.y;
    const int bb = bh >> 4, h = bh & 15;
    const int q0 = blockIdx.x * 128;

    const uint32_t* Qf32 = (const uint32_t*)g_qf + (size_t)bh * SEQ * 32;
    const uint32_t* Kf32 = (const uint32_t*)g_kf + (size_t)bh * SEQ * 32;
    const uint32_t* T32  = (const uint32_t*)g_vtf + (size_t)bh * HDIM * (SEQ / 2);

    const uint32_t smbase = s2u(sm);

    auto aload = [&](int kt, int st) {
        uint32_t base = smbase + (uint32_t)st * 4608u * 4u;
        const int k0 = kt * 64;
        #pragma unroll
        for (int j = 0; j < 2; j++) {
            int idx = tid + j * 256;             // 0..511
            int row = idx >> 3, v = idx & 7;
            uint32_t so = (uint32_t)(row * 36 + v * 4) * 4u;
            cp16(base + so,            Kf32 + (size_t)(k0 + row) * 32 + v * 4);
            cp16(base + 2304u*4u + so, T32 + (size_t)row * (SEQ / 2) + k0 / 2 + v * 4);
        }
    };

    // Q fragments (plain fp16), 16 q-rows per warp, in registers
    unsigned qf[4][4];
    {
        int qr = q0 + warp * 16 + r;
        const uint32_t* rf0 = Qf32 + (size_t)qr * 32;
        const uint32_t* rf8 = Qf32 + (size_t)(qr + 8) * 32;
        #pragma unroll
        for (int kk = 0; kk < 4; kk++) {
            qf[kk][0] = rf0[kk * 8 + c];     qf[kk][1] = rf8[kk * 8 + c];
            qf[kk][2] = rf0[kk * 8 + c + 4]; qf[kk][3] = rf8[kk * 8 + c + 4];
        }
    }

    float o[8][4] = {};
    float lsum_lo = 0.0f, lsum_hi = 0.0f;

    aload(0, 0); CP_COMMIT();
    aload(1, 1); CP_COMMIT();

    for (int kt = 0; kt < SEQ / 64; kt++) {
        const int k0 = kt * 64;

        CP_WAIT1();
        __syncthreads();
        if (kt + 2 < SEQ / 64) aload(kt + 2, (kt + 2) % 3);
        CP_COMMIT();

        unsigned* st = sm + (kt % 3) * 4608;
        unsigned* sK = st;
        unsigned* sV = st + 2304;

        // S = Q K^T (1-term fp16)
        float s[8][4] = {};
        #pragma unroll
        for (int kk = 0; kk < 4; kk++) {
            #pragma unroll
            for (int nt = 0; nt < 8; nt++) {
                int n = nt * 8 + r;
                unsigned b0 = sK[n * 36 + kk * 8 + c];
                unsigned b1 = sK[n * 36 + kk * 8 + c + 4];
                mma_h(s[nt], qf[kk], b0, b1);
            }
        }

        // fixed-max softmax: p = exp(s/8 + mask); accumulate l in registers
        #pragma unroll
        for (int nt = 0; nt < 8; nt++) {
            int col = k0 + nt * 8 + 2 * c;
            float mk0 = __ldg(mask + (size_t)bb * SEQ + col);
            float mk1 = __ldg(mask + (size_t)bb * SEQ + col + 1);
            s[nt][0] = __expf(fmaf(s[nt][0], 0.125f, mk0));
            s[nt][1] = __expf(fmaf(s[nt][1], 0.125f, mk1));
            s[nt][2] = __expf(fmaf(s[nt][2], 0.125f, mk0));
            s[nt][3] = __expf(fmaf(s[nt][3], 0.125f, mk1));
            lsum_lo += s[nt][0] + s[nt][1];
            lsum_hi += s[nt][2] + s[nt][3];
        }

        // P: C-frag layout == A-frag layout; split hi/lo in registers
        unsigned aPh[4][4], aPl[4][4];
        #pragma unroll
        for (int kk = 0; kk < 4; kk++) {
            split2h(s[2*kk][0],   s[2*kk][1],   aPh[kk][0], aPl[kk][0]);
            split2h(s[2*kk][2],   s[2*kk][3],   aPh[kk][1], aPl[kk][1]);
            split2h(s[2*kk+1][0], s[2*kk+1][1], aPh[kk][2], aPl[kk][2]);
            split2h(s[2*kk+1][2], s[2*kk+1][3], aPh[kk][3], aPl[kk][3]);
        }

        // O += P V (2-term), B from smem V^T (plain)
        #pragma unroll
        for (int kk = 0; kk < 4; kk++) {
            #pragma unroll
            for (int nt = 0; nt < 8; nt++) {
                int d = nt * 8 + r;
                unsigned b0 = sV[d * 36 + kk * 8 + c];
                unsigned b1 = sV[d * 36 + kk * 8 + c + 4];
                mma_h(o[nt], aPh[kk], b0, b1);
                mma_h(o[nt], aPl[kk], b0, b1);
            }
        }
    }

    // reduce l across the quad (c=0..3 share the q-row)
    #pragma unroll
    for (int d = 1; d <= 2; d <<= 1) {
        lsum_lo += __shfl_xor_sync(0xffffffffu, lsum_lo, d);
        lsum_hi += __shfl_xor_sync(0xffffffffu, lsum_hi, d);
    }
    float inv_lo = 1.0f / lsum_lo;
    float inv_hi = 1.0f / lsum_hi;

    // write ctx as plain fp16 [m][n]
    uint32_t* Cf = (uint32_t*)g_cxf;
    size_t mrow  = (size_t)bb * SEQ + q0 + warp * 16 + r;
    size_t mrow8 = mrow + 8;
    #pragma unroll
    for (int nt = 0; nt < 8; nt++) {
        int col = h * 64 + nt * 8 + 2 * c;
        Cf[(mrow  * HID + col) / 2] =
            pack2h(__float2half_rn(o[nt][0] * inv_lo), __float2half_rn(o[nt][1] * inv_lo));
        Cf[(mrow8 * HID + col) / 2] =
            pack2h(__float2half_rn(o[nt][2] * inv_hi), __float2half_rn(o[nt][3] * inv_hi));
    }
}

// ---------------------------------------------------------------------------

extern "C" void kernel_launch(void* const* d_in, const int* in_sizes, int n_in,
                              void* d_out, int out_size)
{
    const float* hs   = (const float*)d_in[0];
    const float* mask = (const float*)d_in[1];
    const float* Wq   = (const float*)d_in[2];
    const float* bq   = (const float*)d_in[3];
    const float* Wk   = (const float*)d_in[4];
    const float* bk   = (const float*)d_in[5];
    const float* Wv   = (const float*)d_in[6];
    const float* bv   = (const float*)d_in[7];
    const float* Wo   = (const float*)d_in[8];
    const float* bo   = (const float*)d_in[9];
    float* out = (float*)d_out;

    __half *hsf, *wf, *qf, *kf, *vf, *cxf;
    cudaGetSymbolAddress((void**)&hsf, g_hsf);
    cudaGetSymbolAddress((void**)&wf,  g_wf);
    cudaGetSymbolAddress((void**)&qf,  g_qf);
    cudaGetSymbolAddress((void**)&kf,  g_kf);
    cudaGetSymbolAddress((void**)&vf,  g_vf);
    cudaGetSymbolAddress((void**)&cxf, g_cxf);

    const int gemm_smem = 3 * 3840 * 4;   // 46,080 B
    const int attn_smem = 3 * 4608 * 4;   // 55,296 B
    cudaFuncSetAttribute(gemm16, cudaFuncAttributeMaxDynamicSharedMemorySize, gemm_smem);
    cudaFuncSetAttribute(attn16, cudaFuncAttributeMaxDynamicSharedMemorySize, attn_smem);

    dim3 blk(256);
    const int nHS = MROWS * HID / 4;   // 1,048,576 float4
    const int nW  = HID * HID / 4;     // 262,144 float4

    // prepare operands (all plain fp16)
    conv16<<<nHS / 256, blk>>>((const float4*)hs, (uint2*)hsf, nHS);
    conv16<<<nW / 256, blk>>>((const float4*)Wq, (uint2*)(wf + 0 * HID * HID), nW);
    conv16<<<nW / 256, blk>>>((const float4*)Wk, (uint2*)(wf + 1 * HID * HID), nW);
    conv16<<<nW / 256, blk>>>((const float4*)Wv, (uint2*)(wf + 2 * HID * HID), nW);
    conv16<<<nW / 256, blk>>>((const float4*)Wo, (uint2*)(wf + 3 * HID * HID), nW);

    dim3 gG(HID / 64, MROWS / 128);    // (16, 32)
    gemm16<<<gG, blk, gemm_smem>>>(hsf, wf + 0 * HID * HID, bq, nullptr, qf);
    gemm16<<<gG, blk, gemm_smem>>>(hsf, wf + 1 * HID * HID, bk, nullptr, kf);
    gemm16<<<gG, blk, gemm_smem>>>(hsf, wf + 2 * HID * HID, bv, nullptr, vf);

    dim3 gT(SEQ / 64, BH);             // (32, 32)
    transV<<<gT, blk>>>();

    dim3 gA(SEQ / 128, BH);            // (16, 32)
    attn16<<<gA, blk, attn_smem>>>(mask);

    gemm16<<<gG, blk, gemm_smem>>>(cxf, wf + 3 * HID * HID, bo, out, nullptr);
}

// round 11
// speedup vs baseline: 2.7418x; 1.1321x over previous
#include <cuda_runtime.h>
#include <cuda_fp16.h>
#include <cstdint>

#define BATCH 2
#define SEQ   2048
#define HID   1024
#define NHEAD 16
#define HDIM  64
#define MROWS (BATCH*SEQ)   // 4096
#define BH    (BATCH*NHEAD) // 32

// ---------------- device scratch (allocation-free rule) ----------------
__device__ __half g_hsf[MROWS*HID];                     // hidden states plain fp16
__device__ __half g_wf[4*HID*HID];                      // Wq,Wk,Wv,Wo plain fp16
__device__ __half g_qf[BH*SEQ*HDIM];                    // Q plain [bh][s][d]
__device__ __half g_kf[BH*SEQ*HDIM];                    // K plain [bh][s][d]
__device__ __half g_vf[BH*SEQ*HDIM];                    // V plain [bh][s][d]
__device__ __half g_vtf[BH*HDIM*SEQ];                   // V^T plain [bh][d][s]
__device__ __half g_cxf[MROWS*HID];                     // ctx plain [m][n]

// ---------------- helpers ----------------
__device__ __forceinline__ unsigned pack2h(__half a, __half b) {
    __half2 t(a, b);
    return *reinterpret_cast<unsigned*>(&t);
}
__device__ __forceinline__ void mma_h(float* c, const unsigned* a,
                                      unsigned b0, unsigned b1) {
    asm volatile(
        "mma.sync.aligned.m16n8k16.row.col.f32.f16.f16.f32 "
        "{%0,%1,%2,%3},{%4,%5,%6,%7},{%8,%9},{%0,%1,%2,%3};\n"
        : "+f"(c[0]), "+f"(c[1]), "+f"(c[2]), "+f"(c[3])
        : "r"(a[0]), "r"(a[1]), "r"(a[2]), "r"(a[3]), "r"(b0), "r"(b1));
}
__device__ __forceinline__ uint32_t s2u(const void* p) {
    uint32_t a;
    asm("{ .reg .u64 t; cvta.to.shared.u64 t, %1; cvt.u32.u64 %0, t; }" : "=r"(a) : "l"(p));
    return a;
}
__device__ __forceinline__ void cp16(uint32_t saddr, const void* gaddr) {
    asm volatile("cp.async.cg.shared.global [%0], [%1], 16;" :: "r"(saddr), "l"(gaddr));
}
#define CP_COMMIT() asm volatile("cp.async.commit_group;" ::: "memory")
#define CP_WAIT1()  asm volatile("cp.async.wait_group 1;" ::: "memory")

// ---------------- fp32 -> fp16 plain convert (single tensor) ----------------
__global__ void conv16(const float4* __restrict__ in, uint2* __restrict__ outp, int n4)
{
    int i = blockIdx.x * 256 + threadIdx.x;
    if (i >= n4) return;
    float4 v = in[i];
    uint2 o;
    o.x = pack2h(__float2half_rn(v.x), __float2half_rn(v.y));
    o.y = pack2h(__float2half_rn(v.z), __float2half_rn(v.w));
    outp[i] = o;
}

// ---------------- fp32 -> fp16 convert, 4 weight matrices in one launch ----------------
__global__ void conv16x4(const float4* __restrict__ w0, const float4* __restrict__ w1,
                         const float4* __restrict__ w2, const float4* __restrict__ w3,
                         uint2* __restrict__ outp, int n4)
{
    int i = blockIdx.x * 256 + threadIdx.x;
    if (i >= n4) return;
    const float4* src = (blockIdx.y == 0) ? w0 : (blockIdx.y == 1) ? w1
                      : (blockIdx.y == 2) ? w2 : w3;
    float4 v = src[i];
    uint2 o;
    o.x = pack2h(__float2half_rn(v.x), __float2half_rn(v.y));
    o.y = pack2h(__float2half_rn(v.z), __float2half_rn(v.w));
    outp[(size_t)blockIdx.y * n4 + i] = o;
}

// ---------------- GEMM: C = A @ W^T + bias (1-term plain fp16) ----------------
// tile 128x64, kstep 32 halves. Stage 3840 u32: A @ 0 (128x20), W @ 2560 (64x20).
// outH != nullptr: head-split plain fp16; else fp32 row-major to outF.
__global__ __launch_bounds__(256, 2) void gemm16(
    const __half* __restrict__ Af, const __half* __restrict__ Wf,
    const float* __restrict__ bias, float* __restrict__ outF, __half* __restrict__ outH)
{
    extern __shared__ unsigned sm[];

    const int tid  = threadIdx.x;
    const int lane = tid & 31, warp = tid >> 5;
    const int wm = warp >> 1, wn = warp & 1;
    const int r = lane >> 2, c = lane & 3;
    const int m0 = blockIdx.y * 128, n0 = blockIdx.x * 64;

    const uint32_t* A32 = (const uint32_t*)Af;
    const uint32_t* W32 = (const uint32_t*)Wf;

    const uint32_t smbase = s2u(sm);

    auto gload = [&](int kc, int st) {
        uint32_t base = smbase + (uint32_t)st * 3840u * 4u;
        #pragma unroll
        for (int j = 0; j < 2; j++) {
            int idx = tid + j * 256;             // 0..511
            int row = idx >> 2, v = idx & 3;
            size_t go = (size_t)(m0 + row) * 512 + kc * 16 + v * 4;
            cp16(base + (uint32_t)(row * 20 + v * 4) * 4u, A32 + go);
        }
        {
            int row = tid >> 2, v = tid & 3;
            size_t go = (size_t)(n0 + row) * 512 + kc * 16 + v * 4;
            cp16(base + 2560u*4u + (uint32_t)(row * 20 + v * 4) * 4u, W32 + go);
        }
    };

    float acc[2][4][4] = {};

    gload(0, 0); CP_COMMIT();
    gload(1, 1); CP_COMMIT();

    for (int kc = 0; kc < 32; kc++) {
        CP_WAIT1();
        __syncthreads();
        if (kc + 2 < 32) gload(kc + 2, (kc + 2) % 3);
        CP_COMMIT();

        unsigned* st = sm + (kc % 3) * 3840;
        unsigned* sA = st;
        unsigned* sW = st + 2560;

        #pragma unroll
        for (int kk = 0; kk < 2; kk++) {
            unsigned a[2][4];
            #pragma unroll
            for (int mt = 0; mt < 2; mt++) {
                int base = wm * 32 + mt * 16;
                a[mt][0] = sA[(base + r)     * 20 + kk * 8 + c];
                a[mt][1] = sA[(base + r + 8) * 20 + kk * 8 + c];
                a[mt][2] = sA[(base + r)     * 20 + kk * 8 + c + 4];
                a[mt][3] = sA[(base + r + 8) * 20 + kk * 8 + c + 4];
            }
            #pragma unroll
            for (int nt = 0; nt < 4; nt++) {
                int n = wn * 32 + nt * 8 + r;
                unsigned b0 = sW[n * 20 + kk * 8 + c];
                unsigned b1 = sW[n * 20 + kk * 8 + c + 4];
                #pragma unroll
                for (int mt = 0; mt < 2; mt++)
                    mma_h(acc[mt][nt], a[mt], b0, b1);
            }
        }
    }

    uint32_t* OH32 = (uint32_t*)outH;

    #pragma unroll
    for (int mt = 0; mt < 2; mt++) {
        #pragma unroll
        for (int nt = 0; nt < 4; nt++) {
            int row = m0 + wm * 32 + mt * 16 + r;
            int col = n0 + wn * 32 + nt * 8 + 2 * c;
            float b0v = bias[col], b1v = bias[col + 1];
            float v00 = acc[mt][nt][0] + b0v;
            float v01 = acc[mt][nt][1] + b1v;
            float v10 = acc[mt][nt][2] + b0v;
            float v11 = acc[mt][nt][3] + b1v;
            if (outH == nullptr) {
                outF[(size_t)row * HID + col]           = v00;
                outF[(size_t)row * HID + col + 1]       = v01;
                outF[(size_t)(row + 8) * HID + col]     = v10;
                outF[(size_t)(row + 8) * HID + col + 1] = v11;
            } else {
                int hh = col >> 6, d = col & 63;
                int bb0 = row >> 11, s0 = row & (SEQ - 1);
                int bb1 = (row + 8) >> 11, s1 = (row + 8) & (SEQ - 1);
                size_t o0 = ((((size_t)(bb0 * NHEAD + hh)) * SEQ + s0) * HDIM + d) / 2;
                size_t o1 = ((((size_t)(bb1 * NHEAD + hh)) * SEQ + s1) * HDIM + d) / 2;
                OH32[o0] = pack2h(__float2half_rn(v00), __float2half_rn(v01));
                OH32[o1] = pack2h(__float2half_rn(v10), __float2half_rn(v11));
            }
        }
    }
}

// ---------------- V transpose: [bh][s][d] -> [bh][d][s] (plain) ----------------
__global__ __launch_bounds__(256) void transV()
{
    __shared__ __half t[64][66];
    const int tid = threadIdx.x;
    const int s0  = blockIdx.x * 64;
    const int bh  = blockIdx.y;

    const uint32_t* V32 = (const uint32_t*)g_vf + (size_t)bh * SEQ * 32;
    uint32_t* T32 = (uint32_t*)g_vtf + (size_t)bh * HDIM * (SEQ / 2);

    #pragma unroll
    for (int j = 0; j < 8; j++) {
        int idx = tid + j * 256;
        int row = idx >> 5, p = idx & 31;
        *(uint32_t*)&t[row][2 * p] = V32[(size_t)(s0 + row) * 32 + p];
    }
    __syncthreads();
    #pragma unroll
    for (int j = 0; j < 8; j++) {
        int idx = tid + j * 256;
        int d = idx >> 5, q = idx & 31;
        T32[(size_t)d * (SEQ / 2) + s0 / 2 + q] = pack2h(t[2 * q][d], t[2 * q + 1][d]);
    }
}

// ---------------- fused attention ----------------
// CTA: 128 q-rows of one (b,h), 8 warps x 16 q, 32 k-tiles of 64.
// S = Qf x Kf (1-term). P plain fp16 in regs. PV = Pf x Vf (1-term).
// Stage 4608 u32: K @ 0 (64x36), Vf @ 2304. cp.async 3-stage.
__global__ __launch_bounds__(256, 2) void attn16(const float* __restrict__ mask)
{
    extern __shared__ unsigned sm[];

    const int tid  = threadIdx.x;
    const int lane = tid & 31, warp = tid >> 5;
    const int r = lane >> 2, c = lane & 3;
    const int bh = blockIdx.y;
    const int bb = bh >> 4, h = bh & 15;
    const int q0 = blockIdx.x * 128;

    const uint32_t* Qf32 = (const uint32_t*)g_qf + (size_t)bh * SEQ * 32;
    const uint32_t* Kf32 = (const uint32_t*)g_kf + (size_t)bh * SEQ * 32;
    const uint32_t* T32  = (const uint32_t*)g_vtf + (size_t)bh * HDIM * (SEQ / 2);

    const uint32_t smbase = s2u(sm);

    auto aload = [&](int kt, int st) {
        uint32_t base = smbase + (uint32_t)st * 4608u * 4u;
        const int k0 = kt * 64;
        #pragma unroll
        for (int j = 0; j < 2; j++) {
            int idx = tid + j * 256;             // 0..511
            int row = idx >> 3, v = idx & 7;
            uint32_t so = (uint32_t)(row * 36 + v * 4) * 4u;
            cp16(base + so,            Kf32 + (size_t)(k0 + row) * 32 + v * 4);
            cp16(base + 2304u*4u + so, T32 + (size_t)row * (SEQ / 2) + k0 / 2 + v * 4);
        }
    };

    // Q fragments (plain fp16), 16 q-rows per warp, in registers
    unsigned qf[4][4];
    {
        int qr = q0 + warp * 16 + r;
        const uint32_t* rf0 = Qf32 + (size_t)qr * 32;
        const uint32_t* rf8 = Qf32 + (size_t)(qr + 8) * 32;
        #pragma unroll
        for (int kk = 0; kk < 4; kk++) {
            qf[kk][0] = rf0[kk * 8 + c];     qf[kk][1] = rf8[kk * 8 + c];
            qf[kk][2] = rf0[kk * 8 + c + 4]; qf[kk][3] = rf8[kk * 8 + c + 4];
        }
    }

    float o[8][4] = {};
    float lsum_lo = 0.0f, lsum_hi = 0.0f;

    aload(0, 0); CP_COMMIT();
    aload(1, 1); CP_COMMIT();

    for (int kt = 0; kt < SEQ / 64; kt++) {
        const int k0 = kt * 64;

        CP_WAIT1();
        __syncthreads();
        if (kt + 2 < SEQ / 64) aload(kt + 2, (kt + 2) % 3);
        CP_COMMIT();

        unsigned* st = sm + (kt % 3) * 4608;
        unsigned* sK = st;
        unsigned* sV = st + 2304;

        // S = Q K^T (1-term fp16)
        float s[8][4] = {};
        #pragma unroll
        for (int kk = 0; kk < 4; kk++) {
            #pragma unroll
            for (int nt = 0; nt < 8; nt++) {
                int n = nt * 8 + r;
                unsigned b0 = sK[n * 36 + kk * 8 + c];
                unsigned b1 = sK[n * 36 + kk * 8 + c + 4];
                mma_h(s[nt], qf[kk], b0, b1);
            }
        }

        // fixed-max softmax: p = exp(s/8 + mask); accumulate l in registers
        #pragma unroll
        for (int nt = 0; nt < 8; nt++) {
            int col = k0 + nt * 8 + 2 * c;
            float mk0 = __ldg(mask + (size_t)bb * SEQ + col);
            float mk1 = __ldg(mask + (size_t)bb * SEQ + col + 1);
            s[nt][0] = __expf(fmaf(s[nt][0], 0.125f, mk0));
            s[nt][1] = __expf(fmaf(s[nt][1], 0.125f, mk1));
            s[nt][2] = __expf(fmaf(s[nt][2], 0.125f, mk0));
            s[nt][3] = __expf(fmaf(s[nt][3], 0.125f, mk1));
            lsum_lo += s[nt][0] + s[nt][1];
            lsum_hi += s[nt][2] + s[nt][3];
        }

        // P: C-frag layout == A-frag layout; plain fp16 pack in registers
        unsigned aP[4][4];
        #pragma unroll
        for (int kk = 0; kk < 4; kk++) {
            aP[kk][0] = pack2h(__float2half_rn(s[2*kk][0]),   __float2half_rn(s[2*kk][1]));
            aP[kk][1] = pack2h(__float2half_rn(s[2*kk][2]),   __float2half_rn(s[2*kk][3]));
            aP[kk][2] = pack2h(__float2half_rn(s[2*kk+1][0]), __float2half_rn(s[2*kk+1][1]));
            aP[kk][3] = pack2h(__float2half_rn(s[2*kk+1][2]), __float2half_rn(s[2*kk+1][3]));
        }

        // O += P V (1-term), B from smem V^T (plain)
        #pragma unroll
        for (int kk = 0; kk < 4; kk++) {
            #pragma unroll
            for (int nt = 0; nt < 8; nt++) {
                int d = nt * 8 + r;
                unsigned b0 = sV[d * 36 + kk * 8 + c];
                unsigned b1 = sV[d * 36 + kk * 8 + c + 4];
                mma_h(o[nt], aP[kk], b0, b1);
            }
        }
    }

    // reduce l across the quad (c=0..3 share the q-row)
    #pragma unroll
    for (int d = 1; d <= 2; d <<= 1) {
        lsum_lo += __shfl_xor_sync(0xffffffffu, lsum_lo, d);
        lsum_hi += __shfl_xor_sync(0xffffffffu, lsum_hi, d);
    }
    float inv_lo = 1.0f / lsum_lo;
    float inv_hi = 1.0f / lsum_hi;

    // write ctx as plain fp16 [m][n]
    uint32_t* Cf = (uint32_t*)g_cxf;
    size_t mrow  = (size_t)bb * SEQ + q0 + warp * 16 + r;
    size_t mrow8 = mrow + 8;
    #pragma unroll
    for (int nt = 0; nt < 8; nt++) {
        int col = h * 64 + nt * 8 + 2 * c;
        Cf[(mrow  * HID + col) / 2] =
            pack2h(__float2half_rn(o[nt][0] * inv_lo), __float2half_rn(o[nt][1] * inv_lo));
        Cf[(mrow8 * HID + col) / 2] =
            pack2h(__float2half_rn(o[nt][2] * inv_hi), __float2half_rn(o[nt][3] * inv_hi));
    }
}

// ---------------------------------------------------------------------------

extern "C" void kernel_launch(void* const* d_in, const int* in_sizes, int n_in,
                              void* d_out, int out_size)
{
    const float* hs   = (const float*)d_in[0];
    const float* mask = (const float*)d_in[1];
    const float* Wq   = (const float*)d_in[2];
    const float* bq   = (const float*)d_in[3];
    const float* Wk   = (const float*)d_in[4];
    const float* bk   = (const float*)d_in[5];
    const float* Wv   = (const float*)d_in[6];
    const float* bv   = (const float*)d_in[7];
    const float* Wo   = (const float*)d_in[8];
    const float* bo   = (const float*)d_in[9];
    float* out = (float*)d_out;

    __half *hsf, *wf, *qf, *kf, *vf, *cxf;
    cudaGetSymbolAddress((void**)&hsf, g_hsf);
    cudaGetSymbolAddress((void**)&wf,  g_wf);
    cudaGetSymbolAddress((void**)&qf,  g_qf);
    cudaGetSymbolAddress((void**)&kf,  g_kf);
    cudaGetSymbolAddress((void**)&vf,  g_vf);
    cudaGetSymbolAddress((void**)&cxf, g_cxf);

    const int gemm_smem = 3 * 3840 * 4;   // 46,080 B
    const int attn_smem = 3 * 4608 * 4;   // 55,296 B
    cudaFuncSetAttribute(gemm16, cudaFuncAttributeMaxDynamicSharedMemorySize, gemm_smem);
    cudaFuncSetAttribute(attn16, cudaFuncAttributeMaxDynamicSharedMemorySize, attn_smem);

    dim3 blk(256);
    const int nHS = MROWS * HID / 4;   // 1,048,576 float4
    const int nW  = HID * HID / 4;     // 262,144 float4

    // prepare operands (all plain fp16); weights fused into one launch
    conv16<<<nHS / 256, blk>>>((const float4*)hs, (uint2*)hsf, nHS);
    dim3 gW(nW / 256, 4);
    conv16x4<<<gW, blk>>>((const float4*)Wq, (const float4*)Wk,
                          (const float4*)Wv, (const float4*)Wo, (uint2*)wf, nW);

    dim3 gG(HID / 64, MROWS / 128);    // (16, 32)
    gemm16<<<gG, blk, gemm_smem>>>(hsf, wf + 0 * HID * HID, bq, nullptr, qf);
    gemm16<<<gG, blk, gemm_smem>>>(hsf, wf + 1 * HID * HID, bk, nullptr, kf);
    gemm16<<<gG, blk, gemm_smem>>>(hsf, wf + 2 * HID * HID, bv, nullptr, vf);

    dim3 gT(SEQ / 64, BH);             // (32, 32)
    transV<<<gT, blk>>>();

    dim3 gA(SEQ / 128, BH);            // (16, 32)
    attn16<<<gA, blk, attn_smem>>>(mask);

    gemm16<<<gG, blk, gemm_smem>>>(cxf, wf + 3 * HID * HID, bo, out, nullptr);
}

// round 12
// speedup vs baseline: 3.1820x; 1.1606x over previous
#include <cuda_runtime.h>
#include <cuda_fp16.h>
#include <cstdint>

#define BATCH 2
#define SEQ   2048
#define HID   1024
#define NHEAD 16
#define HDIM  64
#define MROWS (BATCH*SEQ)   // 4096
#define BH    (BATCH*NHEAD) // 32

// ---------------- device scratch (allocation-free rule) ----------------
__device__ __half g_hsf[MROWS*HID];                     // hidden states plain fp16
__device__ __half g_wf[4*HID*HID];                      // Wq,Wk,Wv,Wo plain fp16
__device__ __half g_qf[BH*SEQ*HDIM];                    // Q plain [bh][s][d]
__device__ __half g_kf[BH*SEQ*HDIM];                    // K plain [bh][s][d]
__device__ __half g_vf[BH*SEQ*HDIM];                    // V plain [bh][s][d]
__device__ __half g_vtf[BH*HDIM*SEQ];                   // V^T plain [bh][d][s]
__device__ __half g_cxf[MROWS*HID];                     // ctx plain [m][n]

// ---------------- helpers ----------------
__device__ __forceinline__ unsigned pack2h(__half a, __half b) {
    __half2 t(a, b);
    return *reinterpret_cast<unsigned*>(&t);
}
__device__ __forceinline__ void mma_h(float* c, const unsigned* a,
                                      unsigned b0, unsigned b1) {
    asm volatile(
        "mma.sync.aligned.m16n8k16.row.col.f32.f16.f16.f32 "
        "{%0,%1,%2,%3},{%4,%5,%6,%7},{%8,%9},{%0,%1,%2,%3};\n"
        : "+f"(c[0]), "+f"(c[1]), "+f"(c[2]), "+f"(c[3])
        : "r"(a[0]), "r"(a[1]), "r"(a[2]), "r"(a[3]), "r"(b0), "r"(b1));
}
__device__ __forceinline__ uint32_t s2u(const void* p) {
    uint32_t a;
    asm("{ .reg .u64 t; cvta.to.shared.u64 t, %1; cvt.u32.u64 %0, t; }" : "=r"(a) : "l"(p));
    return a;
}
__device__ __forceinline__ void cp16(uint32_t saddr, const void* gaddr) {
    asm volatile("cp.async.cg.shared.global [%0], [%1], 16;" :: "r"(saddr), "l"(gaddr));
}
#define CP_COMMIT() asm volatile("cp.async.commit_group;" ::: "memory")
#define CP_WAIT1()  asm volatile("cp.async.wait_group 1;" ::: "memory")

// GEMM tile geometry: CTA 128(M) x 128(N), kstep 32 halves (16 u32).
// Stage = A(128x20) + W(128x20) = 5120 u32 = 20 KB. 3 stages.
#define GSTAGE 5120

// ---------------- fp32 -> fp16 plain convert (single tensor) ----------------
__global__ void conv16(const float4* __restrict__ in, uint2* __restrict__ outp, int n4)
{
    int i = blockIdx.x * 256 + threadIdx.x;
    if (i >= n4) return;
    float4 v = in[i];
    uint2 o;
    o.x = pack2h(__float2half_rn(v.x), __float2half_rn(v.y));
    o.y = pack2h(__float2half_rn(v.z), __float2half_rn(v.w));
    outp[i] = o;
}

// ---------------- fp32 -> fp16 convert, 4 weight matrices in one launch ----------------
__global__ void conv16x4(const float4* __restrict__ w0, const float4* __restrict__ w1,
                         const float4* __restrict__ w2, const float4* __restrict__ w3,
                         uint2* __restrict__ outp, int n4)
{
    int i = blockIdx.x * 256 + threadIdx.x;
    if (i >= n4) return;
    const float4* src = (blockIdx.y == 0) ? w0 : (blockIdx.y == 1) ? w1
                      : (blockIdx.y == 2) ? w2 : w3;
    float4 v = src[i];
    uint2 o;
    o.x = pack2h(__float2half_rn(v.x), __float2half_rn(v.y));
    o.y = pack2h(__float2half_rn(v.z), __float2half_rn(v.w));
    outp[(size_t)blockIdx.y * n4 + i] = o;
}

// ---------------- GEMM core macros (tile 128x128, warp-tile 32x64) ----------------
// 8 warps: wm = warp>>1 (0..3) -> m offset, wn = warp&1 -> n offset 64.
// Per kk: 8 a-LDS + 16 b-LDS -> 16 MMA (1.5 LDS/MMA).

// ---------------- fused QKV GEMM: [hs] @ {Wq,Wk,Wv}^T + bias -> head-split fp16 ----------------
__global__ __launch_bounds__(256, 2) void gemmQKV(
    const __half* __restrict__ Af,
    const float* __restrict__ bq, const float* __restrict__ bk, const float* __restrict__ bv)
{
    extern __shared__ unsigned sm[];

    const int tid  = threadIdx.x;
    const int lane = tid & 31, warp = tid >> 5;
    const int wm = warp >> 1, wn = warp & 1;
    const int r = lane >> 2, c = lane & 3;
    const int m0 = blockIdx.y * 128;
    const int ng = blockIdx.x * 128;          // 0..2943 global N over [Q|K|V]
    const int w  = ng >> 10;                  // 0=Q 1=K 2=V
    const int n0 = ng & 1023;

    const uint32_t* A32 = (const uint32_t*)Af;
    const uint32_t* W32 = (const uint32_t*)g_wf + (size_t)w * (HID * HID / 2);
    const float* bias   = (w == 0) ? bq : (w == 1) ? bk : bv;
    uint32_t* OH32      = (uint32_t*)((w == 0) ? g_qf : (w == 1) ? g_kf : g_vf);

    const uint32_t smbase = s2u(sm);

    auto gload = [&](int kc, int st) {
        uint32_t base = smbase + (uint32_t)st * GSTAGE * 4u;
        #pragma unroll
        for (int j = 0; j < 2; j++) {
            int idx = tid + j * 256;             // 0..511
            int row = idx >> 2, v = idx & 3;
            uint32_t so = (uint32_t)(row * 20 + v * 4) * 4u;
            cp16(base + so,               A32 + (size_t)(m0 + row) * 512 + kc * 16 + v * 4);
            cp16(base + 2560u*4u + so,    W32 + (size_t)(n0 + row) * 512 + kc * 16 + v * 4);
        }
    };

    float acc[2][8][4] = {};

    gload(0, 0); CP_COMMIT();
    gload(1, 1); CP_COMMIT();

    for (int kc = 0; kc < 32; kc++) {
        CP_WAIT1();
        __syncthreads();
        if (kc + 2 < 32) gload(kc + 2, (kc + 2) % 3);
        CP_COMMIT();

        unsigned* st = sm + (kc % 3) * GSTAGE;
        unsigned* sA = st;
        unsigned* sW = st + 2560;

        #pragma unroll
        for (int kk = 0; kk < 2; kk++) {
            unsigned a[2][4];
            #pragma unroll
            for (int mt = 0; mt < 2; mt++) {
                int base = wm * 32 + mt * 16;
                a[mt][0] = sA[(base + r)     * 20 + kk * 8 + c];
                a[mt][1] = sA[(base + r + 8) * 20 + kk * 8 + c];
                a[mt][2] = sA[(base + r)     * 20 + kk * 8 + c + 4];
                a[mt][3] = sA[(base + r + 8) * 20 + kk * 8 + c + 4];
            }
            #pragma unroll
            for (int nt = 0; nt < 8; nt++) {
                int n = wn * 64 + nt * 8 + r;
                unsigned b0 = sW[n * 20 + kk * 8 + c];
                unsigned b1 = sW[n * 20 + kk * 8 + c + 4];
                #pragma unroll
                for (int mt = 0; mt < 2; mt++)
                    mma_h(acc[mt][nt], a[mt], b0, b1);
            }
        }
    }

    #pragma unroll
    for (int mt = 0; mt < 2; mt++) {
        #pragma unroll
        for (int nt = 0; nt < 8; nt++) {
            int row = m0 + wm * 32 + mt * 16 + r;
            int col = n0 + wn * 64 + nt * 8 + 2 * c;
            float v00 = acc[mt][nt][0] + bias[col];
            float v01 = acc[mt][nt][1] + bias[col + 1];
            float v10 = acc[mt][nt][2] + bias[col];
            float v11 = acc[mt][nt][3] + bias[col + 1];
            int hh = col >> 6, d = col & 63;
            int bb0 = row >> 11, s0 = row & (SEQ - 1);
            int bb1 = (row + 8) >> 11, s1 = (row + 8) & (SEQ - 1);
            size_t o0 = ((((size_t)(bb0 * NHEAD + hh)) * SEQ + s0) * HDIM + d) / 2;
            size_t o1 = ((((size_t)(bb1 * NHEAD + hh)) * SEQ + s1) * HDIM + d) / 2;
            OH32[o0] = pack2h(__float2half_rn(v00), __float2half_rn(v01));
            OH32[o1] = pack2h(__float2half_rn(v10), __float2half_rn(v11));
        }
    }
}

// ---------------- output GEMM: ctx @ Wo^T + bo -> fp32 ----------------
__global__ __launch_bounds__(256, 2) void gemmO(
    const __half* __restrict__ Af, const float* __restrict__ bias, float* __restrict__ outF)
{
    extern __shared__ unsigned sm[];

    const int tid  = threadIdx.x;
    const int lane = tid & 31, warp = tid >> 5;
    const int wm = warp >> 1, wn = warp & 1;
    const int r = lane >> 2, c = lane & 3;
    const int m0 = blockIdx.y * 128, n0 = blockIdx.x * 128;

    const uint32_t* A32 = (const uint32_t*)Af;
    const uint32_t* W32 = (const uint32_t*)g_wf + 3 * (size_t)(HID * HID / 2);

    const uint32_t smbase = s2u(sm);

    auto gload = [&](int kc, int st) {
        uint32_t base = smbase + (uint32_t)st * GSTAGE * 4u;
        #pragma unroll
        for (int j = 0; j < 2; j++) {
            int idx = tid + j * 256;
            int row = idx >> 2, v = idx & 3;
            uint32_t so = (uint32_t)(row * 20 + v * 4) * 4u;
            cp16(base + so,            A32 + (size_t)(m0 + row) * 512 + kc * 16 + v * 4);
            cp16(base + 2560u*4u + so, W32 + (size_t)(n0 + row) * 512 + kc * 16 + v * 4);
        }
    };

    float acc[2][8][4] = {};

    gload(0, 0); CP_COMMIT();
    gload(1, 1); CP_COMMIT();

    for (int kc = 0; kc < 32; kc++) {
        CP_WAIT1();
        __syncthreads();
        if (kc + 2 < 32) gload(kc + 2, (kc + 2) % 3);
        CP_COMMIT();

        unsigned* st = sm + (kc % 3) * GSTAGE;
        unsigned* sA = st;
        unsigned* sW = st + 2560;

        #pragma unroll
        for (int kk = 0; kk < 2; kk++) {
            unsigned a[2][4];
            #pragma unroll
            for (int mt = 0; mt < 2; mt++) {
                int base = wm * 32 + mt * 16;
                a[mt][0] = sA[(base + r)     * 20 + kk * 8 + c];
                a[mt][1] = sA[(base + r + 8) * 20 + kk * 8 + c];
                a[mt][2] = sA[(base + r)     * 20 + kk * 8 + c + 4];
                a[mt][3] = sA[(base + r + 8) * 20 + kk * 8 + c + 4];
            }
            #pragma unroll
            for (int nt = 0; nt < 8; nt++) {
                int n = wn * 64 + nt * 8 + r;
                unsigned b0 = sW[n * 20 + kk * 8 + c];
                unsigned b1 = sW[n * 20 + kk * 8 + c + 4];
                #pragma unroll
                for (int mt = 0; mt < 2; mt++)
                    mma_h(acc[mt][nt], a[mt], b0, b1);
            }
        }
    }

    #pragma unroll
    for (int mt = 0; mt < 2; mt++) {
        #pragma unroll
        for (int nt = 0; nt < 8; nt++) {
            int row = m0 + wm * 32 + mt * 16 + r;
            int col = n0 + wn * 64 + nt * 8 + 2 * c;
            float b0v = bias[col], b1v = bias[col + 1];
            outF[(size_t)row * HID + col]           = acc[mt][nt][0] + b0v;
            outF[(size_t)row * HID + col + 1]       = acc[mt][nt][1] + b1v;
            outF[(size_t)(row + 8) * HID + col]     = acc[mt][nt][2] + b0v;
            outF[(size_t)(row + 8) * HID + col + 1] = acc[mt][nt][3] + b1v;
        }
    }
}

// ---------------- V transpose: [bh][s][d] -> [bh][d][s] (plain) ----------------
__global__ __launch_bounds__(256) void transV()
{
    __shared__ __half t[64][66];
    const int tid = threadIdx.x;
    const int s0  = blockIdx.x * 64;
    const int bh  = blockIdx.y;

    const uint32_t* V32 = (const uint32_t*)g_vf + (size_t)bh * SEQ * 32;
    uint32_t* T32 = (uint32_t*)g_vtf + (size_t)bh * HDIM * (SEQ / 2);

    #pragma unroll
    for (int j = 0; j < 8; j++) {
        int idx = tid + j * 256;
        int row = idx >> 5, p = idx & 31;
        *(uint32_t*)&t[row][2 * p] = V32[(size_t)(s0 + row) * 32 + p];
    }
    __syncthreads();
    #pragma unroll
    for (int j = 0; j < 8; j++) {
        int idx = tid + j * 256;
        int d = idx >> 5, q = idx & 31;
        T32[(size_t)d * (SEQ / 2) + s0 / 2 + q] = pack2h(t[2 * q][d], t[2 * q + 1][d]);
    }
}

// ---------------- fused attention (unchanged from R11) ----------------
__global__ __launch_bounds__(256, 2) void attn16(const float* __restrict__ mask)
{
    extern __shared__ unsigned sm[];

    const int tid  = threadIdx.x;
    const int lane = tid & 31, warp = tid >> 5;
    const int r = lane >> 2, c = lane & 3;
    const int bh = blockIdx.y;
    const int bb = bh >> 4, h = bh & 15;
    const int q0 = blockIdx.x * 128;

    const uint32_t* Qf32 = (const uint32_t*)g_qf + (size_t)bh * SEQ * 32;
    const uint32_t* Kf32 = (const uint32_t*)g_kf + (size_t)bh * SEQ * 32;
    const uint32_t* T32  = (const uint32_t*)g_vtf + (size_t)bh * HDIM * (SEQ / 2);

    const uint32_t smbase = s2u(sm);

    auto aload = [&](int kt, int st) {
        uint32_t base = smbase + (uint32_t)st * 4608u * 4u;
        const int k0 = kt * 64;
        #pragma unroll
        for (int j = 0; j < 2; j++) {
            int idx = tid + j * 256;             // 0..511
            int row = idx >> 3, v = idx & 7;
            uint32_t so = (uint32_t)(row * 36 + v * 4) * 4u;
            cp16(base + so,            Kf32 + (size_t)(k0 + row) * 32 + v * 4);
            cp16(base + 2304u*4u + so, T32 + (size_t)row * (SEQ / 2) + k0 / 2 + v * 4);
        }
    };

    unsigned qf[4][4];
    {
        int qr = q0 + warp * 16 + r;
        const uint32_t* rf0 = Qf32 + (size_t)qr * 32;
        const uint32_t* rf8 = Qf32 + (size_t)(qr + 8) * 32;
        #pragma unroll
        for (int kk = 0; kk < 4; kk++) {
            qf[kk][0] = rf0[kk * 8 + c];     qf[kk][1] = rf8[kk * 8 + c];
            qf[kk][2] = rf0[kk * 8 + c + 4]; qf[kk][3] = rf8[kk * 8 + c + 4];
        }
    }

    float o[8][4] = {};
    float lsum_lo = 0.0f, lsum_hi = 0.0f;

    aload(0, 0); CP_COMMIT();
    aload(1, 1); CP_COMMIT();

    for (int kt = 0; kt < SEQ / 64; kt++) {
        const int k0 = kt * 64;

        CP_WAIT1();
        __syncthreads();
        if (kt + 2 < SEQ / 64) aload(kt + 2, (kt + 2) % 3);
        CP_COMMIT();

        unsigned* st = sm + (kt % 3) * 4608;
        unsigned* sK = st;
        unsigned* sV = st + 2304;

        float s[8][4] = {};
        #pragma unroll
        for (int kk = 0; kk < 4; kk++) {
            #pragma unroll
            for (int nt = 0; nt < 8; nt++) {
                int n = nt * 8 + r;
                unsigned b0 = sK[n * 36 + kk * 8 + c];
                unsigned b1 = sK[n * 36 + kk * 8 + c + 4];
                mma_h(s[nt], qf[kk], b0, b1);
            }
        }

        #pragma unroll
        for (int nt = 0; nt < 8; nt++) {
            int col = k0 + nt * 8 + 2 * c;
            float mk0 = __ldg(mask + (size_t)bb * SEQ + col);
            float mk1 = __ldg(mask + (size_t)bb * SEQ + col + 1);
            s[nt][0] = __expf(fmaf(s[nt][0], 0.125f, mk0));
            s[nt][1] = __expf(fmaf(s[nt][1], 0.125f, mk1));
            s[nt][2] = __expf(fmaf(s[nt][2], 0.125f, mk0));
            s[nt][3] = __expf(fmaf(s[nt][3], 0.125f, mk1));
            lsum_lo += s[nt][0] + s[nt][1];
            lsum_hi += s[nt][2] + s[nt][3];
        }

        unsigned aP[4][4];
        #pragma unroll
        for (int kk = 0; kk < 4; kk++) {
            aP[kk][0] = pack2h(__float2half_rn(s[2*kk][0]),   __float2half_rn(s[2*kk][1]));
            aP[kk][1] = pack2h(__float2half_rn(s[2*kk][2]),   __float2half_rn(s[2*kk][3]));
            aP[kk][2] = pack2h(__float2half_rn(s[2*kk+1][0]), __float2half_rn(s[2*kk+1][1]));
            aP[kk][3] = pack2h(__float2half_rn(s[2*kk+1][2]), __float2half_rn(s[2*kk+1][3]));
        }

        #pragma unroll
        for (int kk = 0; kk < 4; kk++) {
            #pragma unroll
            for (int nt = 0; nt < 8; nt++) {
                int d = nt * 8 + r;
                unsigned b0 = sV[d * 36 + kk * 8 + c];
                unsigned b1 = sV[d * 36 + kk * 8 + c + 4];
                mma_h(o[nt], aP[kk], b0, b1);
            }
        }
    }

    #pragma unroll
    for (int d = 1; d <= 2; d <<= 1) {
        lsum_lo += __shfl_xor_sync(0xffffffffu, lsum_lo, d);
        lsum_hi += __shfl_xor_sync(0xffffffffu, lsum_hi, d);
    }
    float inv_lo = 1.0f / lsum_lo;
    float inv_hi = 1.0f / lsum_hi;

    uint32_t* Cf = (uint32_t*)g_cxf;
    size_t mrow  = (size_t)bb * SEQ + q0 + warp * 16 + r;
    size_t mrow8 = mrow + 8;
    #pragma unroll
    for (int nt = 0; nt < 8; nt++) {
        int col = h * 64 + nt * 8 + 2 * c;
        Cf[(mrow  * HID + col) / 2] =
            pack2h(__float2half_rn(o[nt][0] * inv_lo), __float2half_rn(o[nt][1] * inv_lo));
        Cf[(mrow8 * HID + col) / 2] =
            pack2h(__float2half_rn(o[nt][2] * inv_hi), __float2half_rn(o[nt][3] * inv_hi));
    }
}

// ---------------------------------------------------------------------------

extern "C" void kernel_launch(void* const* d_in, const int* in_sizes, int n_in,
                              void* d_out, int out_size)
{
    const float* hs   = (const float*)d_in[0];
    const float* mask = (const float*)d_in[1];
    const float* Wq   = (const float*)d_in[2];
    const float* bq   = (const float*)d_in[3];
    const float* Wk   = (const float*)d_in[4];
    const float* bk   = (const float*)d_in[5];
    const float* Wv   = (const float*)d_in[6];
    const float* bv   = (const float*)d_in[7];
    const float* Wo   = (const float*)d_in[8];
    const float* bo   = (const float*)d_in[9];
    float* out = (float*)d_out;

    __half *hsf, *wf, *cxf;
    cudaGetSymbolAddress((void**)&hsf, g_hsf);
    cudaGetSymbolAddress((void**)&wf,  g_wf);
    cudaGetSymbolAddress((void**)&cxf, g_cxf);

    const int gemm_smem = 3 * GSTAGE * 4;   // 61,440 B
    const int attn_smem = 3 * 4608 * 4;     // 55,296 B
    cudaFuncSetAttribute(gemmQKV, cudaFuncAttributeMaxDynamicSharedMemorySize, gemm_smem);
    cudaFuncSetAttribute(gemmO,   cudaFuncAttributeMaxDynamicSharedMemorySize, gemm_smem);
    cudaFuncSetAttribute(attn16,  cudaFuncAttributeMaxDynamicSharedMemorySize, attn_smem);

    dim3 blk(256);
    const int nHS = MROWS * HID / 4;   // 1,048,576 float4
    const int nW  = HID * HID / 4;     // 262,144 float4

    conv16<<<nHS / 256, blk>>>((const float4*)hs, (uint2*)hsf, nHS);
    dim3 gW(nW / 256, 4);
    conv16x4<<<gW, blk>>>((const float4*)Wq, (const float4*)Wk,
                          (const float4*)Wv, (const float4*)Wo, (uint2*)wf, nW);

    dim3 gQKV(3 * HID / 128, MROWS / 128);   // (24, 32) = 768 CTAs
    gemmQKV<<<gQKV, blk, gemm_smem>>>(hsf, bq, bk, bv);

    dim3 gT(SEQ / 64, BH);                   // (32, 32)
    transV<<<gT, blk>>>();

    dim3 gA(SEQ / 128, BH);                  // (16, 32)
    attn16<<<gA, blk, attn_smem>>>(mask);

    dim3 gO(HID / 128, MROWS / 128);         // (8, 32) = 256 CTAs, single wave
    gemmO<<<gO, blk, gemm_smem>>>(cxf, bo, out);
}